// round 11
// baseline (speedup 1.0000x reference)
#include <cuda_runtime.h>
#include <cuda_fp16.h>
#include <math.h>
#include <stdint.h>

// Problem constants
#define BATCH   2
#define SEQ     2048
#define HID     2048
#define NHEADS  16
#define HDIM    128
#define MROWS   (BATCH*SEQ)        // 4096
#define EPSV    1e-6f

// ---------------------------------------------------------------------------
// Scratch (__device__ globals; no cudaMalloc allowed)
// ---------------------------------------------------------------------------
__device__ __half g_xh  [MROWS*HID];     // rmsnorm out
__device__ __half g_ctxh[MROWS*HID];     // attention out
__device__ __half g_qh  [MROWS*HID];     // fp16 GEMM outs
__device__ __half g_kh  [MROWS*HID];
__device__ __half g_vh  [MROWS*HID];
__device__ __half g_g1h [MROWS*HID];
__device__ __half g_g3h [MROWS*HID];
__device__ __half g_sx  [MROWS*HID];     // silu out
__device__ __half g_Wq2[HID*HID];        // transposed fp16 weights [N][K]
__device__ __half g_Wk2[HID*HID];
__device__ __half g_Wv2[HID*HID];
__device__ __half g_Wo2[HID*HID];
__device__ __half g_w12[HID*HID];
__device__ __half g_w22[HID*HID];
__device__ __half g_w32[HID*HID];
__device__ float g_h  [MROWS*HID];
__device__ float g_cos[SEQ*64];
__device__ float g_sin[SEQ*64];
// attention operands (fp16, head-major)
__device__ __half g_q2 [(size_t)BATCH*NHEADS*SEQ*HDIM];  // [bh][s][128]
__device__ __half g_k2 [(size_t)BATCH*NHEADS*SEQ*HDIM];  // [bh][s][128]
__device__ __half g_vt [(size_t)BATCH*NHEADS*HDIM*SEQ];  // [bh][d][s]

// ---------------------------------------------------------------------------
// Helpers
// ---------------------------------------------------------------------------
__device__ __forceinline__ uint32_t smem_u32(const void* p) {
    uint32_t a;
    asm("{ .reg .u64 t; cvta.to.shared.u64 t, %1; cvt.u32.u64 %0, t; }" : "=r"(a) : "l"(p));
    return a;
}
__device__ __forceinline__ uint32_t packh(float x, float y) {
    __half2 t = __floats2half2_rn(x, y);
    return *(uint32_t*)&t;
}
__device__ __forceinline__ void cpasync16(uint32_t dst, const void* src) {
    asm volatile("cp.async.cg.shared.global [%0], [%1], 16;" :: "r"(dst), "l"(src));
}
__device__ __forceinline__ void ldm_x4(uint32_t& r0, uint32_t& r1, uint32_t& r2, uint32_t& r3,
                                       uint32_t addr) {
    asm volatile("ldmatrix.sync.aligned.m8n8.x4.shared.b16 {%0,%1,%2,%3}, [%4];"
                 : "=r"(r0), "=r"(r1), "=r"(r2), "=r"(r3) : "r"(addr));
}
__device__ __forceinline__ void mma16816h(float* c, const uint32_t* a, const uint32_t* b) {
    asm volatile(
        "mma.sync.aligned.m16n8k16.row.col.f32.f16.f16.f32 "
        "{%0,%1,%2,%3}, {%4,%5,%6,%7}, {%8,%9}, {%0,%1,%2,%3};"
        : "+f"(c[0]), "+f"(c[1]), "+f"(c[2]), "+f"(c[3])
        : "r"(a[0]), "r"(a[1]), "r"(a[2]), "r"(a[3]), "r"(b[0]), "r"(b[1]));
}

// ---------------------------------------------------------------------------
// RoPE cos/sin table
// ---------------------------------------------------------------------------
__global__ void rope_table_kernel() {
    int idx = blockIdx.x * 256 + threadIdx.x;
    if (idx < SEQ * 64) {
        int s = idx >> 6, i = idx & 63;
        double inv = pow(10000.0, -((double)(2 * i)) / 128.0);
        double ang = (double)s * inv;
        g_cos[idx] = (float)cos(ang);
        g_sin[idx] = (float)sin(ang);
    }
}

// ---------------------------------------------------------------------------
// RMSNorm -> fp16 (2048 wide)
// ---------------------------------------------------------------------------
__global__ __launch_bounds__(256) void rmsnorm_h_kernel(
    const float* __restrict__ x, const float* __restrict__ w, __half* __restrict__ outh)
{
    int row = blockIdx.x;
    const float4* xr = (const float4*)(x + (size_t)row * HID);
    float4 v0 = xr[threadIdx.x];
    float4 v1 = xr[threadIdx.x + 256];
    float ss = v0.x*v0.x + v0.y*v0.y + v0.z*v0.z + v0.w*v0.w
             + v1.x*v1.x + v1.y*v1.y + v1.z*v1.z + v1.w*v1.w;
    #pragma unroll
    for (int m = 16; m; m >>= 1) ss += __shfl_xor_sync(0xffffffffu, ss, m);
    __shared__ float red[8];
    if ((threadIdx.x & 31) == 0) red[threadIdx.x >> 5] = ss;
    __syncthreads();
    float tot = red[0] + red[1] + red[2] + red[3] + red[4] + red[5] + red[6] + red[7];
    float sc = rsqrtf(tot * (1.0f / (float)HID) + EPSV);
    const float4* wv = (const float4*)w;
    float4 w0 = wv[threadIdx.x];
    float4 w1v = wv[threadIdx.x + 256];
    __half* orow = outh + (size_t)row * HID;
    int c0 = threadIdx.x * 4, c1 = c0 + 1024;
    *(__half2*)&orow[c0]     = __floats2half2_rn(v0.x*sc*w0.x,  v0.y*sc*w0.y);
    *(__half2*)&orow[c0 + 2] = __floats2half2_rn(v0.z*sc*w0.z,  v0.w*sc*w0.w);
    *(__half2*)&orow[c1]     = __floats2half2_rn(v1.x*sc*w1v.x, v1.y*sc*w1v.y);
    *(__half2*)&orow[c1 + 2] = __floats2half2_rn(v1.z*sc*w1v.z, v1.w*sc*w1v.w);
}

// ---------------------------------------------------------------------------
// Batched weight transpose: 7x W[K][N] f32 -> B[N][K] fp16. 64x64 tiles.
// ---------------------------------------------------------------------------
struct WArgs { const float* src[7]; __half* dst[7]; };

__global__ __launch_bounds__(256) void wtrans_all_kernel(WArgs args) {
    const float* W = args.src[blockIdx.z];
    __half* B = args.dst[blockIdx.z];
    __shared__ float t[64][65];
    int bn = blockIdx.x * 64;   // n-tile
    int bk = blockIdx.y * 64;   // k-tile
    int tid = threadIdx.x;
    #pragma unroll
    for (int i = 0; i < 4; i++) {
        int idx = tid + 256*i;
        int r_ = idx >> 4, c4 = idx & 15;       // 16 float4 per 64-wide row
        float4 vv = *(const float4*)(W + (size_t)(bk + r_) * HID + bn + c4*4);
        t[r_][c4*4+0] = vv.x; t[r_][c4*4+1] = vv.y;
        t[r_][c4*4+2] = vv.z; t[r_][c4*4+3] = vv.w;
    }
    __syncthreads();
    int n_ = tid >> 2, kc = (tid & 3) * 16;
    __half* orow = B + (size_t)(bn + n_) * HID + bk + kc;
    #pragma unroll
    for (int j = 0; j < 16; j += 2)
        *(__half2*)(orow + j) = __floats2half2_rn(t[kc + j][n_], t[kc + j + 1][n_]);
}

// ---------------------------------------------------------------------------
// HMMA fp16 GEMM: C[4096 x 2048] = A @ B^T (+Dd). Tile 128(M) x 256(N), BK=32.
// 8 warps, warp tile 64x64. 4-stage cp.async, occ 1.
// Output: fp32 C (with optional residual Dd) OR fp16 Ch (one of C/Ch null).
// FIX vs R9/R10: second cp.async of each 16-half run goes to smem +16 BYTES
// (8 halves), not +32.
// ---------------------------------------------------------------------------
#define ASTRIDE 40
#define A_HALVES (128*ASTRIDE)               // 5120
#define B_HALVES (256*ASTRIDE)               // 10240
#define STGB ((A_HALVES + B_HALVES)*2)       // 30720 bytes
#define NSTG 4
#define GEMM_SMEM (NSTG*STGB)                // 122880
#define KITERS (HID/32)                      // 64

__global__ __launch_bounds__(256, 1) void hmma_gemm_kernel(
    const __half* __restrict__ A, const __half* __restrict__ B,
    const float* __restrict__ Dd, float* __restrict__ C, __half* __restrict__ Ch)
{
    extern __shared__ char smraw[];
    uint32_t smb = smem_u32(smraw);
    int tid = threadIdx.x, wid = tid >> 5, lid = tid & 31;
    int mt = blockIdx.x, nt = blockIdx.y;

    // load mapping: A 2 x 16B per thread (16 contiguous halves), B 4 x 16B
    int lrow = tid >> 1;
    int seg0 = (tid & 1) * 2;                // halves offset seg0*8 .. +16
    const __half* aptr = A + (size_t)(mt*128 + lrow) * HID + seg0*8;
    const __half* bptr0 = B + (size_t)(nt*256 + lrow) * HID + seg0*8;
    const __half* bptr1 = B + (size_t)(nt*256 + lrow + 128) * HID + seg0*8;
    uint32_t aoff  = (uint32_t)(lrow*ASTRIDE + seg0*8) * 2;
    uint32_t boff0 = (uint32_t)(A_HALVES + lrow*ASTRIDE + seg0*8) * 2;
    uint32_t boff1 = (uint32_t)(A_HALVES + (lrow + 128)*ASTRIDE + seg0*8) * 2;

    #define LOADIT(it_) do {                                            \
        uint32_t sb_ = smb + (uint32_t)((it_) & 3) * STGB;              \
        int k0_ = (it_) * 32;                                           \
        cpasync16(sb_ + aoff,       aptr  + k0_);                       \
        cpasync16(sb_ + aoff  + 16, aptr  + k0_ + 8);                   \
        cpasync16(sb_ + boff0,      bptr0 + k0_);                       \
        cpasync16(sb_ + boff0 + 16, bptr0 + k0_ + 8);                   \
        cpasync16(sb_ + boff1,      bptr1 + k0_);                       \
        cpasync16(sb_ + boff1 + 16, bptr1 + k0_ + 8);                   \
    } while (0)

    int m0w = (wid & 1) * 64, n0w = (wid >> 1) * 64;
    int g = lid >> 3, r = lid & 7;
    uint32_t aBaseH = (uint32_t)((m0w + r + (g & 1)*8) * ASTRIDE + (g >> 1)*8);
    uint32_t bBaseH = (uint32_t)(A_HALVES + (n0w + r + (g >> 1)*8) * ASTRIDE + (g & 1)*8);

    float acc[4][8][4];
    #pragma unroll
    for (int mi = 0; mi < 4; mi++)
        #pragma unroll
        for (int ni = 0; ni < 8; ni++)
            #pragma unroll
            for (int e = 0; e < 4; e++) acc[mi][ni][e] = 0.0f;

    #pragma unroll
    for (int s = 0; s < 3; s++) {
        LOADIT(s);
        asm volatile("cp.async.commit_group;");
    }

    for (int it = 0; it < KITERS; it++) {
        asm volatile("cp.async.wait_group 2;");
        __syncthreads();
        uint32_t sb = smb + (uint32_t)(it & 3) * STGB;
        #pragma unroll
        for (int ks = 0; ks < 32; ks += 16) {
            uint32_t b[8][2];
            #pragma unroll
            for (int np = 0; np < 4; np++) {
                uint32_t r0, r1, r2, r3;
                ldm_x4(r0, r1, r2, r3, sb + 2*(bBaseH + (uint32_t)(np*16*ASTRIDE) + ks));
                b[np*2][0] = r0;   b[np*2][1] = r1;
                b[np*2+1][0] = r2; b[np*2+1][1] = r3;
            }
            #pragma unroll
            for (int mi = 0; mi < 4; mi++) {
                uint32_t a[4];
                ldm_x4(a[0], a[1], a[2], a[3], sb + 2*(aBaseH + (uint32_t)(mi*16*ASTRIDE) + ks));
                #pragma unroll
                for (int ni = 0; ni < 8; ni++) mma16816h(acc[mi][ni], a, b[ni]);
            }
        }
        int itn = it + 3;
        if (itn < KITERS) LOADIT(itn);
        asm volatile("cp.async.commit_group;");
    }

    int lr = lid >> 2, lc = (lid & 3) * 2;
    #pragma unroll
    for (int mi = 0; mi < 4; mi++) {
        #pragma unroll
        for (int ni = 0; ni < 8; ni++) {
            int row0 = mt*128 + m0w + mi*16 + lr;
            int col  = nt*256 + n0w + ni*8 + lc;
            if (Ch) {
                *(__half2*)(Ch + (size_t)row0 * HID + col) =
                    __floats2half2_rn(acc[mi][ni][0], acc[mi][ni][1]);
                *(__half2*)(Ch + (size_t)(row0 + 8) * HID + col) =
                    __floats2half2_rn(acc[mi][ni][2], acc[mi][ni][3]);
            } else {
                float2 v0 = make_float2(acc[mi][ni][0], acc[mi][ni][1]);
                float2 v1 = make_float2(acc[mi][ni][2], acc[mi][ni][3]);
                if (Dd) {
                    float2 d0 = *(const float2*)(Dd + (size_t)row0 * HID + col);
                    float2 d1 = *(const float2*)(Dd + (size_t)(row0 + 8) * HID + col);
                    v0.x += d0.x; v0.y += d0.y;
                    v1.x += d1.x; v1.y += d1.y;
                }
                *(float2*)(C + (size_t)row0 * HID + col)       = v0;
                *(float2*)(C + (size_t)(row0 + 8) * HID + col) = v1;
            }
        }
    }
    #undef LOADIT
}

// ---------------------------------------------------------------------------
// RoPE + scale: fp16 q,k [token][hid] -> fp16 head-major [bh][s][128]
// ---------------------------------------------------------------------------
__global__ __launch_bounds__(256) void rope_h_kernel(
    const __half* __restrict__ q, const __half* __restrict__ k,
    __half* __restrict__ q2g, __half* __restrict__ k2g)
{
    int token = blockIdx.x;                  // b*SEQ + s
    int b = token >> 11, s = token & (SEQ-1);
    const __half* qr = q + (size_t)token * HID;
    const __half* kr = k + (size_t)token * HID;
    const float qs = 0.08838834764831845f;   // 1/sqrt(128)
    for (int idx = threadIdx.x; idx < NHEADS*64; idx += 256) {
        int h = idx >> 6, i = idx & 63;
        float c  = g_cos[s*64 + i];
        float sn = g_sin[s*64 + i];
        float q1 = __half2float(qr[h*HDIM + i]), q2v = __half2float(qr[h*HDIM + i + 64]);
        float k1 = __half2float(kr[h*HDIM + i]), k2v = __half2float(kr[h*HDIM + i + 64]);
        __half* qd = q2g + ((size_t)(b*NHEADS + h)*SEQ + s) * HDIM;
        __half* kd = k2g + ((size_t)(b*NHEADS + h)*SEQ + s) * HDIM;
        qd[i]    = __float2half_rn((q1*c - q2v*sn) * qs);
        qd[i+64] = __float2half_rn((q2v*c + q1*sn) * qs);
        kd[i]    = __float2half_rn(k1*c - k2v*sn);
        kd[i+64] = __float2half_rn(k2v*c + k1*sn);
    }
}

// ---------------------------------------------------------------------------
// V transpose: fp16 v[b*s][h*128+d] -> fp16 vt[bh][d][s]
// ---------------------------------------------------------------------------
__global__ __launch_bounds__(256) void vconv_kernel(
    const __half* __restrict__ v, __half* __restrict__ vtg)
{
    __shared__ __half t[32][34];
    int s0 = blockIdx.x * 32, d0 = blockIdx.y * 32, bh = blockIdx.z;
    int b = bh >> 4, h = bh & 15;
    int tx = threadIdx.x & 31, ty = threadIdx.x >> 5;
    #pragma unroll
    for (int i = 0; i < 4; i++)
        t[ty + 8*i][tx] = v[(size_t)(b*SEQ + s0 + ty + 8*i) * HID + h*HDIM + d0 + tx];
    __syncthreads();
    __half* vb = vtg + (size_t)bh * HDIM * SEQ;
    #pragma unroll
    for (int i = 0; i < 4; i++) {
        int d = d0 + ty + 8*i;
        vb[(size_t)d*SEQ + s0 + tx] = t[tx][ty + 8*i];
    }
}

// ---------------------------------------------------------------------------
// HMMA flash attention, single-pass fp16 (proven in R7/R8).
// ---------------------------------------------------------------------------
#define QS_STR 136
#define KS_STR 136
#define VS_STR 72
#define QS_OFF 0
#define KS_OFF (128*QS_STR)              // halves
#define KS_SZ  (64*KS_STR)
#define VS_OFF (KS_OFF + 2*KS_SZ)
#define VS_SZ  (128*VS_STR)
#define ATTN_SMEM ((VS_OFF + 2*VS_SZ)*2) // 106496 bytes

__global__ __launch_bounds__(256, 1) void attn_hmma_kernel(
    const __half* __restrict__ q2g, const __half* __restrict__ k2g,
    const __half* __restrict__ vtg, __half* __restrict__ ctxh)
{
    extern __shared__ char smraw[];
    uint32_t smb = smem_u32(smraw);
    int tid = threadIdx.x, wid = tid >> 5, lid = tid & 31;
    int qt = blockIdx.x, hh = blockIdx.y, b = blockIdx.z;
    int bh = b*NHEADS + hh;
    const __half* qbase = q2g + ((size_t)bh*SEQ + qt*128) * HDIM;
    const __half* kbase = k2g + (size_t)bh*SEQ * HDIM;
    const __half* vbase = vtg + (size_t)bh*HDIM*SEQ;

    #define LOAD_KT(st_, s0_) do {                                              \
        _Pragma("unroll")                                                       \
        for (int i_ = 0; i_ < 4; i_++) {                                        \
            int idx_ = tid + 256*i_; int row_ = idx_ >> 4, seg_ = idx_ & 15;    \
            cpasync16(smb + 2*(KS_OFF + (st_)*KS_SZ + row_*KS_STR + seg_*8),    \
                      kbase + ((size_t)((s0_) + row_))*HDIM + seg_*8);          \
        } } while (0)
    #define LOAD_VT(st_, s0_) do {                                              \
        _Pragma("unroll")                                                       \
        for (int i_ = 0; i_ < 4; i_++) {                                        \
            int idx_ = tid + 256*i_; int dr_ = idx_ >> 3, seg_ = idx_ & 7;      \
            cpasync16(smb + 2*(VS_OFF + (st_)*VS_SZ + dr_*VS_STR + seg_*8),     \
                      vbase + (size_t)dr_*SEQ + (s0_) + seg_*8);                \
        } } while (0)

    #pragma unroll
    for (int i = 0; i < 8; i++) {
        int idx = tid + 256*i; int row = idx >> 4, seg = idx & 15;
        cpasync16(smb + 2*(QS_OFF + row*QS_STR + seg*8),
                  qbase + (size_t)row*HDIM + seg*8);
    }
    LOAD_KT(0, 0); LOAD_VT(0, 0);
    asm volatile("cp.async.commit_group;");
    LOAD_KT(1, 64); LOAD_VT(1, 64);
    asm volatile("cp.async.commit_group;");

    int g = lid >> 3, r = lid & 7;
    uint32_t aQ = smb + 2*(QS_OFF + (uint32_t)((wid*16 + r + (g&1)*8)*QS_STR + (g>>1)*8));
    uint32_t bK = smb + 2*(KS_OFF + (uint32_t)((r + (g>>1)*8)*KS_STR + (g&1)*8));
    uint32_t bV = smb + 2*(VS_OFF + (uint32_t)((r + (g>>1)*8)*VS_STR + (g&1)*8));

    float oacc[16][4];
    #pragma unroll
    for (int n = 0; n < 16; n++)
        #pragma unroll
        for (int e = 0; e < 4; e++) oacc[n][e] = 0.0f;
    float m0 = -INFINITY, m1 = -INFINITY, l0 = 0.0f, l1 = 0.0f;

    for (int it = 0; it < SEQ/64; it++) {
        asm volatile("cp.async.wait_group 1;");
        __syncthreads();
        uint32_t kst = (uint32_t)((it & 1) * KS_SZ) * 2;
        uint32_t vst = (uint32_t)((it & 1) * VS_SZ) * 2;

        float sacc[8][4];
        #pragma unroll
        for (int n = 0; n < 8; n++)
            #pragma unroll
            for (int e = 0; e < 4; e++) sacc[n][e] = 0.0f;

        #pragma unroll
        for (int ks = 0; ks < 8; ks++) {
            uint32_t bfr[8][2];
            #pragma unroll
            for (int np = 0; np < 4; np++) {
                uint32_t r0,r1,r2,r3;
                ldm_x4(r0,r1,r2,r3, bK + kst + 2*(uint32_t)(np*16*KS_STR + ks*16));
                bfr[np*2][0]=r0; bfr[np*2][1]=r1; bfr[np*2+1][0]=r2; bfr[np*2+1][1]=r3;
            }
            uint32_t a[4];
            ldm_x4(a[0],a[1],a[2],a[3], aQ + 2*(uint32_t)(ks*16));
            #pragma unroll
            for (int n = 0; n < 8; n++) mma16816h(sacc[n], a, bfr[n]);
        }

        float mt0 = -INFINITY, mt1 = -INFINITY;
        #pragma unroll
        for (int n = 0; n < 8; n++) {
            mt0 = fmaxf(mt0, fmaxf(sacc[n][0], sacc[n][1]));
            mt1 = fmaxf(mt1, fmaxf(sacc[n][2], sacc[n][3]));
        }
        mt0 = fmaxf(mt0, __shfl_xor_sync(0xffffffffu, mt0, 1));
        mt0 = fmaxf(mt0, __shfl_xor_sync(0xffffffffu, mt0, 2));
        mt1 = fmaxf(mt1, __shfl_xor_sync(0xffffffffu, mt1, 1));
        mt1 = fmaxf(mt1, __shfl_xor_sync(0xffffffffu, mt1, 2));
        float mn0 = fmaxf(m0, mt0), mn1 = fmaxf(m1, mt1);
        float al0 = __expf(m0 - mn0), al1 = __expf(m1 - mn1);
        m0 = mn0; m1 = mn1;

        uint32_t ph0[8], ph1[8];
        float rs0 = 0.0f, rs1 = 0.0f;
        #pragma unroll
        for (int n = 0; n < 8; n++) {
            float p0 = __expf(sacc[n][0] - mn0);
            float p1 = __expf(sacc[n][1] - mn0);
            float p2 = __expf(sacc[n][2] - mn1);
            float p3 = __expf(sacc[n][3] - mn1);
            rs0 += p0 + p1; rs1 += p2 + p3;
            ph0[n] = packh(p0, p1);
            ph1[n] = packh(p2, p3);
        }
        rs0 += __shfl_xor_sync(0xffffffffu, rs0, 1);
        rs0 += __shfl_xor_sync(0xffffffffu, rs0, 2);
        rs1 += __shfl_xor_sync(0xffffffffu, rs1, 1);
        rs1 += __shfl_xor_sync(0xffffffffu, rs1, 2);
        l0 = l0*al0 + rs0; l1 = l1*al1 + rs1;
        #pragma unroll
        for (int n = 0; n < 16; n++) {
            oacc[n][0] *= al0; oacc[n][1] *= al0;
            oacc[n][2] *= al1; oacc[n][3] *= al1;
        }

        #pragma unroll
        for (int ks = 0; ks < 4; ks++) {
            uint32_t a[4] = { ph0[2*ks], ph1[2*ks], ph0[2*ks+1], ph1[2*ks+1] };
            #pragma unroll
            for (int np = 0; np < 8; np++) {
                uint32_t r0,r1,r2,r3;
                ldm_x4(r0,r1,r2,r3, bV + vst + 2*(uint32_t)(np*16*VS_STR + ks*16));
                uint32_t b0[2] = {r0, r1}, b1[2] = {r2, r3};
                mma16816h(oacc[np*2], a, b0); mma16816h(oacc[np*2+1], a, b1);
            }
        }

        __syncthreads();
        int itn = it + 2;
        if (itn < SEQ/64) {
            LOAD_KT(itn & 1, itn*64); LOAD_VT(itn & 1, itn*64);
        }
        asm volatile("cp.async.commit_group;");
    }

    float inv0 = 1.0f / l0, inv1 = 1.0f / l1;
    int row0 = qt*128 + wid*16 + (lid >> 2);
    int colb = 2*(lid & 3);
    __half* cb = ctxh + ((size_t)(b*SEQ) + row0) * HID + hh*HDIM;
    #pragma unroll
    for (int n = 0; n < 16; n++) {
        *(__half2*)(cb + n*8 + colb) =
            __floats2half2_rn(oacc[n][0]*inv0, oacc[n][1]*inv0);
        *(__half2*)(cb + (size_t)8*HID + n*8 + colb) =
            __floats2half2_rn(oacc[n][2]*inv1, oacc[n][3]*inv1);
    }
    #undef LOAD_KT
    #undef LOAD_VT
}

// ---------------------------------------------------------------------------
// silu(g1)*g3, fp16 in -> fp16 out
// ---------------------------------------------------------------------------
__global__ __launch_bounds__(256) void silu_h_kernel(
    const __half* __restrict__ g1, const __half* __restrict__ g3, __half* __restrict__ outh)
{
    int i = blockIdx.x * 256 + threadIdx.x;  // half2-pair index (4 halves)
    if (i >= MROWS * HID / 4) return;
    __half2 a0 = ((const __half2*)g1)[2*i],   a1 = ((const __half2*)g1)[2*i+1];
    __half2 b0 = ((const __half2*)g3)[2*i],   b1 = ((const __half2*)g3)[2*i+1];
    float ax = __low2float(a0), ay = __high2float(a0);
    float az = __low2float(a1), aw = __high2float(a1);
    float vx = (ax / (1.0f + expf(-ax))) * __low2float(b0);
    float vy = (ay / (1.0f + expf(-ay))) * __high2float(b0);
    float vz = (az / (1.0f + expf(-az))) * __low2float(b1);
    float vw = (aw / (1.0f + expf(-aw))) * __high2float(b1);
    __half2* o = (__half2*)(outh + (size_t)i * 4);
    o[0] = __floats2half2_rn(vx, vy);
    o[1] = __floats2half2_rn(vz, vw);
}

// ---------------------------------------------------------------------------
// Launch
// ---------------------------------------------------------------------------
extern "C" void kernel_launch(void* const* d_in, const int* in_sizes, int n_in,
                              void* d_out, int out_size)
{
    (void)in_sizes; (void)n_in; (void)out_size;
    const float* hs  = (const float*)d_in[0];
    const float* Wq  = (const float*)d_in[1];
    const float* Wk  = (const float*)d_in[2];
    const float* Wv  = (const float*)d_in[3];
    const float* Wo  = (const float*)d_in[4];
    const float* w1  = (const float*)d_in[5];
    const float* w2  = (const float*)d_in[6];
    const float* w3  = (const float*)d_in[7];
    const float* ln1 = (const float*)d_in[8];
    const float* ln2 = (const float*)d_in[9];
    float* out = (float*)d_out;

    __half *xh, *ctxh, *qh, *kh, *vh, *g1h, *g3h, *sx;
    __half *Wq2, *Wk2, *Wv2, *Wo2, *w12, *w22, *w32;
    __half *q2, *k2, *vt;
    float *h;
    cudaGetSymbolAddress((void**)&xh,   g_xh);
    cudaGetSymbolAddress((void**)&ctxh, g_ctxh);
    cudaGetSymbolAddress((void**)&qh,   g_qh);
    cudaGetSymbolAddress((void**)&kh,   g_kh);
    cudaGetSymbolAddress((void**)&vh,   g_vh);
    cudaGetSymbolAddress((void**)&g1h,  g_g1h);
    cudaGetSymbolAddress((void**)&g3h,  g_g3h);
    cudaGetSymbolAddress((void**)&sx,   g_sx);
    cudaGetSymbolAddress((void**)&Wq2,  g_Wq2);
    cudaGetSymbolAddress((void**)&Wk2,  g_Wk2);
    cudaGetSymbolAddress((void**)&Wv2,  g_Wv2);
    cudaGetSymbolAddress((void**)&Wo2,  g_Wo2);
    cudaGetSymbolAddress((void**)&w12,  g_w12);
    cudaGetSymbolAddress((void**)&w22,  g_w22);
    cudaGetSymbolAddress((void**)&w32,  g_w32);
    cudaGetSymbolAddress((void**)&q2,   g_q2);
    cudaGetSymbolAddress((void**)&k2,   g_k2);
    cudaGetSymbolAddress((void**)&vt,   g_vt);
    cudaGetSymbolAddress((void**)&h,    g_h);

    cudaFuncSetAttribute(attn_hmma_kernel, cudaFuncAttributeMaxDynamicSharedMemorySize, ATTN_SMEM);
    cudaFuncSetAttribute(hmma_gemm_kernel, cudaFuncAttributeMaxDynamicSharedMemorySize, GEMM_SMEM);

    dim3 gemm_grid(MROWS / 128, HID / 256);      // (32, 8)
    int nv4 = MROWS * HID / 4;

    WArgs wa;
    wa.src[0] = Wq; wa.dst[0] = Wq2;
    wa.src[1] = Wk; wa.dst[1] = Wk2;
    wa.src[2] = Wv; wa.dst[2] = Wv2;
    wa.src[3] = Wo; wa.dst[3] = Wo2;
    wa.src[4] = w1; wa.dst[4] = w12;
    wa.src[5] = w2; wa.dst[5] = w22;
    wa.src[6] = w3; wa.dst[6] = w32;

    rope_table_kernel<<<(SEQ * 64 + 255) / 256, 256>>>();
    wtrans_all_kernel<<<dim3(HID/64, HID/64, 7), 256>>>(wa);

    rmsnorm_h_kernel<<<MROWS, 256>>>(hs, ln1, xh);

    hmma_gemm_kernel<<<gemm_grid, 256, GEMM_SMEM>>>(xh, Wq2, nullptr, nullptr, qh);
    hmma_gemm_kernel<<<gemm_grid, 256, GEMM_SMEM>>>(xh, Wk2, nullptr, nullptr, kh);
    hmma_gemm_kernel<<<gemm_grid, 256, GEMM_SMEM>>>(xh, Wv2, nullptr, nullptr, vh);

    rope_h_kernel<<<MROWS, 256>>>(qh, kh, q2, k2);
    vconv_kernel<<<dim3(SEQ/32, HDIM/32, BATCH*NHEADS), 256>>>(vh, vt);

    attn_hmma_kernel<<<dim3(SEQ/128, NHEADS, BATCH), 256, ATTN_SMEM>>>(q2, k2, vt, ctxh);

    hmma_gemm_kernel<<<gemm_grid, 256, GEMM_SMEM>>>(ctxh, Wo2, hs, h, nullptr);  // h = hs + ctx@Wo

    rmsnorm_h_kernel<<<MROWS, 256>>>(h, ln2, xh);                                // y

    hmma_gemm_kernel<<<gemm_grid, 256, GEMM_SMEM>>>(xh, w12, nullptr, nullptr, g1h);
    hmma_gemm_kernel<<<gemm_grid, 256, GEMM_SMEM>>>(xh, w32, nullptr, nullptr, g3h);

    silu_h_kernel<<<(nv4 + 255) / 256, 256>>>(g1h, g3h, sx);

    hmma_gemm_kernel<<<gemm_grid, 256, GEMM_SMEM>>>(sx, w22, h, out, nullptr);   // out = h + mlp
}

// round 12
// speedup vs baseline: 1.0735x; 1.0735x over previous
#include <cuda_runtime.h>
#include <cuda_fp16.h>
#include <math.h>
#include <stdint.h>

// Problem constants
#define BATCH   2
#define SEQ     2048
#define HID     2048
#define NHEADS  16
#define HDIM    128
#define MROWS   (BATCH*SEQ)        // 4096
#define EPSV    1e-6f

// ---------------------------------------------------------------------------
// Scratch (__device__ globals; no cudaMalloc allowed)
// ---------------------------------------------------------------------------
__device__ __half g_xh  [MROWS*HID];     // rmsnorm out
__device__ __half g_ctxh[MROWS*HID];     // attention out
__device__ __half g_qh  [MROWS*HID];     // fp16 GEMM outs
__device__ __half g_kh  [MROWS*HID];
__device__ __half g_vh  [MROWS*HID];
__device__ __half g_g1h [MROWS*HID];
__device__ __half g_g3h [MROWS*HID];
__device__ __half g_sx  [MROWS*HID];     // silu out
__device__ __half g_Wq2[HID*HID];        // transposed fp16 weights [N][K]
__device__ __half g_Wk2[HID*HID];
__device__ __half g_Wv2[HID*HID];
__device__ __half g_Wo2[HID*HID];
__device__ __half g_w12[HID*HID];
__device__ __half g_w22[HID*HID];
__device__ __half g_w32[HID*HID];
__device__ float g_h  [MROWS*HID];
__device__ float g_cos[SEQ*64];
__device__ float g_sin[SEQ*64];
// attention operands (fp16, head-major)
__device__ __half g_q2 [(size_t)BATCH*NHEADS*SEQ*HDIM];  // [bh][s][128]
__device__ __half g_k2 [(size_t)BATCH*NHEADS*SEQ*HDIM];  // [bh][s][128]
__device__ __half g_vt [(size_t)BATCH*NHEADS*HDIM*SEQ];  // [bh][d][s]

// ---------------------------------------------------------------------------
// Helpers
// ---------------------------------------------------------------------------
__device__ __forceinline__ uint32_t smem_u32(const void* p) {
    uint32_t a;
    asm("{ .reg .u64 t; cvta.to.shared.u64 t, %1; cvt.u32.u64 %0, t; }" : "=r"(a) : "l"(p));
    return a;
}
__device__ __forceinline__ uint32_t packh(float x, float y) {
    __half2 t = __floats2half2_rn(x, y);
    return *(uint32_t*)&t;
}
__device__ __forceinline__ void cpasync16(uint32_t dst, const void* src) {
    asm volatile("cp.async.cg.shared.global [%0], [%1], 16;" :: "r"(dst), "l"(src));
}
__device__ __forceinline__ void ldm_x4(uint32_t& r0, uint32_t& r1, uint32_t& r2, uint32_t& r3,
                                       uint32_t addr) {
    asm volatile("ldmatrix.sync.aligned.m8n8.x4.shared.b16 {%0,%1,%2,%3}, [%4];"
                 : "=r"(r0), "=r"(r1), "=r"(r2), "=r"(r3) : "r"(addr));
}
__device__ __forceinline__ void mma16816h(float* c, const uint32_t* a, const uint32_t* b) {
    asm volatile(
        "mma.sync.aligned.m16n8k16.row.col.f32.f16.f16.f32 "
        "{%0,%1,%2,%3}, {%4,%5,%6,%7}, {%8,%9}, {%0,%1,%2,%3};"
        : "+f"(c[0]), "+f"(c[1]), "+f"(c[2]), "+f"(c[3])
        : "r"(a[0]), "r"(a[1]), "r"(a[2]), "r"(a[3]), "r"(b[0]), "r"(b[1]));
}

// ---------------------------------------------------------------------------
// RoPE cos/sin table
// ---------------------------------------------------------------------------
__global__ void rope_table_kernel() {
    int idx = blockIdx.x * 256 + threadIdx.x;
    if (idx < SEQ * 64) {
        int s = idx >> 6, i = idx & 63;
        double inv = pow(10000.0, -((double)(2 * i)) / 128.0);
        double ang = (double)s * inv;
        g_cos[idx] = (float)cos(ang);
        g_sin[idx] = (float)sin(ang);
    }
}

// ---------------------------------------------------------------------------
// RMSNorm -> fp16 (2048 wide)
// ---------------------------------------------------------------------------
__global__ __launch_bounds__(256) void rmsnorm_h_kernel(
    const float* __restrict__ x, const float* __restrict__ w, __half* __restrict__ outh)
{
    int row = blockIdx.x;
    const float4* xr = (const float4*)(x + (size_t)row * HID);
    float4 v0 = xr[threadIdx.x];
    float4 v1 = xr[threadIdx.x + 256];
    float ss = v0.x*v0.x + v0.y*v0.y + v0.z*v0.z + v0.w*v0.w
             + v1.x*v1.x + v1.y*v1.y + v1.z*v1.z + v1.w*v1.w;
    #pragma unroll
    for (int m = 16; m; m >>= 1) ss += __shfl_xor_sync(0xffffffffu, ss, m);
    __shared__ float red[8];
    if ((threadIdx.x & 31) == 0) red[threadIdx.x >> 5] = ss;
    __syncthreads();
    float tot = red[0] + red[1] + red[2] + red[3] + red[4] + red[5] + red[6] + red[7];
    float sc = rsqrtf(tot * (1.0f / (float)HID) + EPSV);
    const float4* wv = (const float4*)w;
    float4 w0 = wv[threadIdx.x];
    float4 w1v = wv[threadIdx.x + 256];
    __half* orow = outh + (size_t)row * HID;
    int c0 = threadIdx.x * 4, c1 = c0 + 1024;
    *(__half2*)&orow[c0]     = __floats2half2_rn(v0.x*sc*w0.x,  v0.y*sc*w0.y);
    *(__half2*)&orow[c0 + 2] = __floats2half2_rn(v0.z*sc*w0.z,  v0.w*sc*w0.w);
    *(__half2*)&orow[c1]     = __floats2half2_rn(v1.x*sc*w1v.x, v1.y*sc*w1v.y);
    *(__half2*)&orow[c1 + 2] = __floats2half2_rn(v1.z*sc*w1v.z, v1.w*sc*w1v.w);
}

// ---------------------------------------------------------------------------
// Batched weight transpose: 7x W[K][N] f32 -> B[N][K] fp16. 64x64 tiles.
// ---------------------------------------------------------------------------
struct WArgs { const float* src[7]; __half* dst[7]; };

__global__ __launch_bounds__(256) void wtrans_all_kernel(WArgs args) {
    const float* W = args.src[blockIdx.z];
    __half* B = args.dst[blockIdx.z];
    __shared__ float t[64][65];
    int bn = blockIdx.x * 64;   // n-tile
    int bk = blockIdx.y * 64;   // k-tile
    int tid = threadIdx.x;
    #pragma unroll
    for (int i = 0; i < 4; i++) {
        int idx = tid + 256*i;
        int r_ = idx >> 4, c4 = idx & 15;       // 16 float4 per 64-wide row
        float4 vv = *(const float4*)(W + (size_t)(bk + r_) * HID + bn + c4*4);
        t[r_][c4*4+0] = vv.x; t[r_][c4*4+1] = vv.y;
        t[r_][c4*4+2] = vv.z; t[r_][c4*4+3] = vv.w;
    }
    __syncthreads();
    int n_ = tid >> 2, kc = (tid & 3) * 16;
    __half* orow = B + (size_t)(bn + n_) * HID + bk + kc;
    #pragma unroll
    for (int j = 0; j < 16; j += 2)
        *(__half2*)(orow + j) = __floats2half2_rn(t[kc + j][n_], t[kc + j + 1][n_]);
}

// ---------------------------------------------------------------------------
// HMMA fp16 GEMM (R8-proven geometry): C[4096 x 2048] = A @ B^T (+Dd).
// Tile 128x128, BK=32, 8 warps (warp tile 64x32), 4-stage cp.async, occ 2.
// Output: fp32 C (+ optional Dd residual) OR fp16 Ch.
// ---------------------------------------------------------------------------
#define ASTRIDE 40
#define STG_HALVES (128*ASTRIDE)
#define STGB ((STG_HALVES*2)*2)             // 20480 bytes
#define NSTG 4
#define GEMM_SMEM (NSTG*STGB)               // 81920
#define KITERS (HID/32)                     // 64

__global__ __launch_bounds__(256, 2) void hmma_gemm_kernel(
    const __half* __restrict__ A, const __half* __restrict__ B,
    const float* __restrict__ Dd, float* __restrict__ C, __half* __restrict__ Ch)
{
    extern __shared__ char smraw[];
    uint32_t smb = smem_u32(smraw);
    int tid = threadIdx.x, wid = tid >> 5, lid = tid & 31;
    int mt = blockIdx.x, nt = blockIdx.y;

    int lrow0 = tid >> 2, lrow1 = lrow0 + 64;
    int seg = tid & 3;
    const __half* aptr0 = A + (size_t)(mt*128 + lrow0) * HID + seg*8;
    const __half* aptr1 = A + (size_t)(mt*128 + lrow1) * HID + seg*8;
    const __half* bptr0 = B + (size_t)(nt*128 + lrow0) * HID + seg*8;
    const __half* bptr1 = B + (size_t)(nt*128 + lrow1) * HID + seg*8;
    uint32_t aoff0 = (uint32_t)(lrow0*ASTRIDE + seg*8) * 2;
    uint32_t aoff1 = (uint32_t)(lrow1*ASTRIDE + seg*8) * 2;
    uint32_t boff0 = (uint32_t)(STG_HALVES + lrow0*ASTRIDE + seg*8) * 2;
    uint32_t boff1 = (uint32_t)(STG_HALVES + lrow1*ASTRIDE + seg*8) * 2;

    #define LOADIT(it_) do {                                            \
        uint32_t sb_ = smb + (uint32_t)((it_) & 3) * STGB;              \
        int k0_ = (it_) * 32;                                           \
        cpasync16(sb_ + aoff0, aptr0 + k0_);                            \
        cpasync16(sb_ + aoff1, aptr1 + k0_);                            \
        cpasync16(sb_ + boff0, bptr0 + k0_);                            \
        cpasync16(sb_ + boff1, bptr1 + k0_);                            \
    } while (0)

    int m0w = (wid & 1) * 64, n0w = (wid >> 1) * 32;
    int g = lid >> 3, r = lid & 7;
    uint32_t aBaseH = (uint32_t)((m0w + r + (g & 1)*8) * ASTRIDE + (g >> 1)*8);
    uint32_t bBaseH = (uint32_t)(STG_HALVES + (n0w + r + (g >> 1)*8) * ASTRIDE + (g & 1)*8);

    float acc[4][4][4];
    #pragma unroll
    for (int mi = 0; mi < 4; mi++)
        #pragma unroll
        for (int ni = 0; ni < 4; ni++)
            #pragma unroll
            for (int e = 0; e < 4; e++) acc[mi][ni][e] = 0.0f;

    #pragma unroll
    for (int s = 0; s < 3; s++) {
        LOADIT(s);
        asm volatile("cp.async.commit_group;");
    }

    for (int it = 0; it < KITERS; it++) {
        asm volatile("cp.async.wait_group 2;");
        __syncthreads();
        uint32_t sb = smb + (uint32_t)(it & 3) * STGB;
        #pragma unroll
        for (int ks = 0; ks < 32; ks += 16) {
            uint32_t b[4][2];
            #pragma unroll
            for (int np = 0; np < 2; np++) {
                uint32_t r0, r1, r2, r3;
                ldm_x4(r0, r1, r2, r3, sb + 2*(bBaseH + (uint32_t)(np*16*ASTRIDE) + ks));
                b[np*2][0] = r0;   b[np*2][1] = r1;
                b[np*2+1][0] = r2; b[np*2+1][1] = r3;
            }
            #pragma unroll
            for (int mi = 0; mi < 4; mi++) {
                uint32_t a[4];
                ldm_x4(a[0], a[1], a[2], a[3], sb + 2*(aBaseH + (uint32_t)(mi*16*ASTRIDE) + ks));
                #pragma unroll
                for (int ni = 0; ni < 4; ni++) mma16816h(acc[mi][ni], a, b[ni]);
            }
        }
        int itn = it + 3;
        if (itn < KITERS) LOADIT(itn);
        asm volatile("cp.async.commit_group;");
    }

    int lr = lid >> 2, lc = (lid & 3) * 2;
    #pragma unroll
    for (int mi = 0; mi < 4; mi++) {
        #pragma unroll
        for (int ni = 0; ni < 4; ni++) {
            int row0 = mt*128 + m0w + mi*16 + lr;
            int col  = nt*128 + n0w + ni*8 + lc;
            if (Ch) {
                *(__half2*)(Ch + (size_t)row0 * HID + col) =
                    __floats2half2_rn(acc[mi][ni][0], acc[mi][ni][1]);
                *(__half2*)(Ch + (size_t)(row0 + 8) * HID + col) =
                    __floats2half2_rn(acc[mi][ni][2], acc[mi][ni][3]);
            } else {
                float2 v0 = make_float2(acc[mi][ni][0], acc[mi][ni][1]);
                float2 v1 = make_float2(acc[mi][ni][2], acc[mi][ni][3]);
                if (Dd) {
                    float2 d0 = *(const float2*)(Dd + (size_t)row0 * HID + col);
                    float2 d1 = *(const float2*)(Dd + (size_t)(row0 + 8) * HID + col);
                    v0.x += d0.x; v0.y += d0.y;
                    v1.x += d1.x; v1.y += d1.y;
                }
                *(float2*)(C + (size_t)row0 * HID + col)       = v0;
                *(float2*)(C + (size_t)(row0 + 8) * HID + col) = v1;
            }
        }
    }
    #undef LOADIT
}

// ---------------------------------------------------------------------------
// RoPE + scale: fp16 q,k [token][hid] -> fp16 head-major [bh][s][128]
// ---------------------------------------------------------------------------
__global__ __launch_bounds__(256) void rope_h_kernel(
    const __half* __restrict__ q, const __half* __restrict__ k,
    __half* __restrict__ q2g, __half* __restrict__ k2g)
{
    int token = blockIdx.x;                  // b*SEQ + s
    int b = token >> 11, s = token & (SEQ-1);
    const __half* qr = q + (size_t)token * HID;
    const __half* kr = k + (size_t)token * HID;
    const float qs = 0.08838834764831845f;   // 1/sqrt(128)
    for (int idx = threadIdx.x; idx < NHEADS*64; idx += 256) {
        int h = idx >> 6, i = idx & 63;
        float c  = g_cos[s*64 + i];
        float sn = g_sin[s*64 + i];
        float q1 = __half2float(qr[h*HDIM + i]), q2v = __half2float(qr[h*HDIM + i + 64]);
        float k1 = __half2float(kr[h*HDIM + i]), k2v = __half2float(kr[h*HDIM + i + 64]);
        __half* qd = q2g + ((size_t)(b*NHEADS + h)*SEQ + s) * HDIM;
        __half* kd = k2g + ((size_t)(b*NHEADS + h)*SEQ + s) * HDIM;
        qd[i]    = __float2half_rn((q1*c - q2v*sn) * qs);
        qd[i+64] = __float2half_rn((q2v*c + q1*sn) * qs);
        kd[i]    = __float2half_rn(k1*c - k2v*sn);
        kd[i+64] = __float2half_rn(k2v*c + k1*sn);
    }
}

// ---------------------------------------------------------------------------
// V transpose: fp16 v[b*s][h*128+d] -> fp16 vt[bh][d][s]
// ---------------------------------------------------------------------------
__global__ __launch_bounds__(256) void vconv_kernel(
    const __half* __restrict__ v, __half* __restrict__ vtg)
{
    __shared__ __half t[32][34];
    int s0 = blockIdx.x * 32, d0 = blockIdx.y * 32, bh = blockIdx.z;
    int b = bh >> 4, h = bh & 15;
    int tx = threadIdx.x & 31, ty = threadIdx.x >> 5;
    #pragma unroll
    for (int i = 0; i < 4; i++)
        t[ty + 8*i][tx] = v[(size_t)(b*SEQ + s0 + ty + 8*i) * HID + h*HDIM + d0 + tx];
    __syncthreads();
    __half* vb = vtg + (size_t)bh * HDIM * SEQ;
    #pragma unroll
    for (int i = 0; i < 4; i++) {
        int d = d0 + ty + 8*i;
        vb[(size_t)d*SEQ + s0 + tx] = t[tx][ty + 8*i];
    }
}

// ---------------------------------------------------------------------------
// HMMA flash attention, single-pass fp16 (proven in R7/R8).
// ---------------------------------------------------------------------------
#define QS_STR 136
#define KS_STR 136
#define VS_STR 72
#define QS_OFF 0
#define KS_OFF (128*QS_STR)              // halves
#define KS_SZ  (64*KS_STR)
#define VS_OFF (KS_OFF + 2*KS_SZ)
#define VS_SZ  (128*VS_STR)
#define ATTN_SMEM ((VS_OFF + 2*VS_SZ)*2) // 106496 bytes

__global__ __launch_bounds__(256, 1) void attn_hmma_kernel(
    const __half* __restrict__ q2g, const __half* __restrict__ k2g,
    const __half* __restrict__ vtg, __half* __restrict__ ctxh)
{
    extern __shared__ char smraw[];
    uint32_t smb = smem_u32(smraw);
    int tid = threadIdx.x, wid = tid >> 5, lid = tid & 31;
    int qt = blockIdx.x, hh = blockIdx.y, b = blockIdx.z;
    int bh = b*NHEADS + hh;
    const __half* qbase = q2g + ((size_t)bh*SEQ + qt*128) * HDIM;
    const __half* kbase = k2g + (size_t)bh*SEQ * HDIM;
    const __half* vbase = vtg + (size_t)bh*HDIM*SEQ;

    #define LOAD_KT(st_, s0_) do {                                              \
        _Pragma("unroll")                                                       \
        for (int i_ = 0; i_ < 4; i_++) {                                        \
            int idx_ = tid + 256*i_; int row_ = idx_ >> 4, seg_ = idx_ & 15;    \
            cpasync16(smb + 2*(KS_OFF + (st_)*KS_SZ + row_*KS_STR + seg_*8),    \
                      kbase + ((size_t)((s0_) + row_))*HDIM + seg_*8);          \
        } } while (0)
    #define LOAD_VT(st_, s0_) do {                                              \
        _Pragma("unroll")                                                       \
        for (int i_ = 0; i_ < 4; i_++) {                                        \
            int idx_ = tid + 256*i_; int dr_ = idx_ >> 3, seg_ = idx_ & 7;      \
            cpasync16(smb + 2*(VS_OFF + (st_)*VS_SZ + dr_*VS_STR + seg_*8),     \
                      vbase + (size_t)dr_*SEQ + (s0_) + seg_*8);                \
        } } while (0)

    #pragma unroll
    for (int i = 0; i < 8; i++) {
        int idx = tid + 256*i; int row = idx >> 4, seg = idx & 15;
        cpasync16(smb + 2*(QS_OFF + row*QS_STR + seg*8),
                  qbase + (size_t)row*HDIM + seg*8);
    }
    LOAD_KT(0, 0); LOAD_VT(0, 0);
    asm volatile("cp.async.commit_group;");
    LOAD_KT(1, 64); LOAD_VT(1, 64);
    asm volatile("cp.async.commit_group;");

    int g = lid >> 3, r = lid & 7;
    uint32_t aQ = smb + 2*(QS_OFF + (uint32_t)((wid*16 + r + (g&1)*8)*QS_STR + (g>>1)*8));
    uint32_t bK = smb + 2*(KS_OFF + (uint32_t)((r + (g>>1)*8)*KS_STR + (g&1)*8));
    uint32_t bV = smb + 2*(VS_OFF + (uint32_t)((r + (g>>1)*8)*VS_STR + (g&1)*8));

    float oacc[16][4];
    #pragma unroll
    for (int n = 0; n < 16; n++)
        #pragma unroll
        for (int e = 0; e < 4; e++) oacc[n][e] = 0.0f;
    float m0 = -INFINITY, m1 = -INFINITY, l0 = 0.0f, l1 = 0.0f;

    for (int it = 0; it < SEQ/64; it++) {
        asm volatile("cp.async.wait_group 1;");
        __syncthreads();
        uint32_t kst = (uint32_t)((it & 1) * KS_SZ) * 2;
        uint32_t vst = (uint32_t)((it & 1) * VS_SZ) * 2;

        float sacc[8][4];
        #pragma unroll
        for (int n = 0; n < 8; n++)
            #pragma unroll
            for (int e = 0; e < 4; e++) sacc[n][e] = 0.0f;

        #pragma unroll
        for (int ks = 0; ks < 8; ks++) {
            uint32_t bfr[8][2];
            #pragma unroll
            for (int np = 0; np < 4; np++) {
                uint32_t r0,r1,r2,r3;
                ldm_x4(r0,r1,r2,r3, bK + kst + 2*(uint32_t)(np*16*KS_STR + ks*16));
                bfr[np*2][0]=r0; bfr[np*2][1]=r1; bfr[np*2+1][0]=r2; bfr[np*2+1][1]=r3;
            }
            uint32_t a[4];
            ldm_x4(a[0],a[1],a[2],a[3], aQ + 2*(uint32_t)(ks*16));
            #pragma unroll
            for (int n = 0; n < 8; n++) mma16816h(sacc[n], a, bfr[n]);
        }

        float mt0 = -INFINITY, mt1 = -INFINITY;
        #pragma unroll
        for (int n = 0; n < 8; n++) {
            mt0 = fmaxf(mt0, fmaxf(sacc[n][0], sacc[n][1]));
            mt1 = fmaxf(mt1, fmaxf(sacc[n][2], sacc[n][3]));
        }
        mt0 = fmaxf(mt0, __shfl_xor_sync(0xffffffffu, mt0, 1));
        mt0 = fmaxf(mt0, __shfl_xor_sync(0xffffffffu, mt0, 2));
        mt1 = fmaxf(mt1, __shfl_xor_sync(0xffffffffu, mt1, 1));
        mt1 = fmaxf(mt1, __shfl_xor_sync(0xffffffffu, mt1, 2));
        float mn0 = fmaxf(m0, mt0), mn1 = fmaxf(m1, mt1);
        float al0 = __expf(m0 - mn0), al1 = __expf(m1 - mn1);
        m0 = mn0; m1 = mn1;

        uint32_t ph0[8], ph1[8];
        float rs0 = 0.0f, rs1 = 0.0f;
        #pragma unroll
        for (int n = 0; n < 8; n++) {
            float p0 = __expf(sacc[n][0] - mn0);
            float p1 = __expf(sacc[n][1] - mn0);
            float p2 = __expf(sacc[n][2] - mn1);
            float p3 = __expf(sacc[n][3] - mn1);
            rs0 += p0 + p1; rs1 += p2 + p3;
            ph0[n] = packh(p0, p1);
            ph1[n] = packh(p2, p3);
        }
        rs0 += __shfl_xor_sync(0xffffffffu, rs0, 1);
        rs0 += __shfl_xor_sync(0xffffffffu, rs0, 2);
        rs1 += __shfl_xor_sync(0xffffffffu, rs1, 1);
        rs1 += __shfl_xor_sync(0xffffffffu, rs1, 2);
        l0 = l0*al0 + rs0; l1 = l1*al1 + rs1;
        #pragma unroll
        for (int n = 0; n < 16; n++) {
            oacc[n][0] *= al0; oacc[n][1] *= al0;
            oacc[n][2] *= al1; oacc[n][3] *= al1;
        }

        #pragma unroll
        for (int ks = 0; ks < 4; ks++) {
            uint32_t a[4] = { ph0[2*ks], ph1[2*ks], ph0[2*ks+1], ph1[2*ks+1] };
            #pragma unroll
            for (int np = 0; np < 8; np++) {
                uint32_t r0,r1,r2,r3;
                ldm_x4(r0,r1,r2,r3, bV + vst + 2*(uint32_t)(np*16*VS_STR + ks*16));
                uint32_t b0[2] = {r0, r1}, b1[2] = {r2, r3};
                mma16816h(oacc[np*2], a, b0); mma16816h(oacc[np*2+1], a, b1);
            }
        }

        __syncthreads();
        int itn = it + 2;
        if (itn < SEQ/64) {
            LOAD_KT(itn & 1, itn*64); LOAD_VT(itn & 1, itn*64);
        }
        asm volatile("cp.async.commit_group;");
    }

    float inv0 = 1.0f / l0, inv1 = 1.0f / l1;
    int row0 = qt*128 + wid*16 + (lid >> 2);
    int colb = 2*(lid & 3);
    __half* cb = ctxh + ((size_t)(b*SEQ) + row0) * HID + hh*HDIM;
    #pragma unroll
    for (int n = 0; n < 16; n++) {
        *(__half2*)(cb + n*8 + colb) =
            __floats2half2_rn(oacc[n][0]*inv0, oacc[n][1]*inv0);
        *(__half2*)(cb + (size_t)8*HID + n*8 + colb) =
            __floats2half2_rn(oacc[n][2]*inv1, oacc[n][3]*inv1);
    }
    #undef LOAD_KT
    #undef LOAD_VT
}

// ---------------------------------------------------------------------------
// silu(g1)*g3, fp16 in -> fp16 out
// ---------------------------------------------------------------------------
__global__ __launch_bounds__(256) void silu_h_kernel(
    const __half* __restrict__ g1, const __half* __restrict__ g3, __half* __restrict__ outh)
{
    int i = blockIdx.x * 256 + threadIdx.x;  // half2-pair index (4 halves)
    if (i >= MROWS * HID / 4) return;
    __half2 a0 = ((const __half2*)g1)[2*i],   a1 = ((const __half2*)g1)[2*i+1];
    __half2 b0 = ((const __half2*)g3)[2*i],   b1 = ((const __half2*)g3)[2*i+1];
    float ax = __low2float(a0), ay = __high2float(a0);
    float az = __low2float(a1), aw = __high2float(a1);
    float vx = (ax / (1.0f + expf(-ax))) * __low2float(b0);
    float vy = (ay / (1.0f + expf(-ay))) * __high2float(b0);
    float vz = (az / (1.0f + expf(-az))) * __low2float(b1);
    float vw = (aw / (1.0f + expf(-aw))) * __high2float(b1);
    __half2* o = (__half2*)(outh + (size_t)i * 4);
    o[0] = __floats2half2_rn(vx, vy);
    o[1] = __floats2half2_rn(vz, vw);
}

// ---------------------------------------------------------------------------
// Launch
// ---------------------------------------------------------------------------
extern "C" void kernel_launch(void* const* d_in, const int* in_sizes, int n_in,
                              void* d_out, int out_size)
{
    (void)in_sizes; (void)n_in; (void)out_size;
    const float* hs  = (const float*)d_in[0];
    const float* Wq  = (const float*)d_in[1];
    const float* Wk  = (const float*)d_in[2];
    const float* Wv  = (const float*)d_in[3];
    const float* Wo  = (const float*)d_in[4];
    const float* w1  = (const float*)d_in[5];
    const float* w2  = (const float*)d_in[6];
    const float* w3  = (const float*)d_in[7];
    const float* ln1 = (const float*)d_in[8];
    const float* ln2 = (const float*)d_in[9];
    float* out = (float*)d_out;

    __half *xh, *ctxh, *qh, *kh, *vh, *g1h, *g3h, *sx;
    __half *Wq2, *Wk2, *Wv2, *Wo2, *w12, *w22, *w32;
    __half *q2, *k2, *vt;
    float *h;
    cudaGetSymbolAddress((void**)&xh,   g_xh);
    cudaGetSymbolAddress((void**)&ctxh, g_ctxh);
    cudaGetSymbolAddress((void**)&qh,   g_qh);
    cudaGetSymbolAddress((void**)&kh,   g_kh);
    cudaGetSymbolAddress((void**)&vh,   g_vh);
    cudaGetSymbolAddress((void**)&g1h,  g_g1h);
    cudaGetSymbolAddress((void**)&g3h,  g_g3h);
    cudaGetSymbolAddress((void**)&sx,   g_sx);
    cudaGetSymbolAddress((void**)&Wq2,  g_Wq2);
    cudaGetSymbolAddress((void**)&Wk2,  g_Wk2);
    cudaGetSymbolAddress((void**)&Wv2,  g_Wv2);
    cudaGetSymbolAddress((void**)&Wo2,  g_Wo2);
    cudaGetSymbolAddress((void**)&w12,  g_w12);
    cudaGetSymbolAddress((void**)&w22,  g_w22);
    cudaGetSymbolAddress((void**)&w32,  g_w32);
    cudaGetSymbolAddress((void**)&q2,   g_q2);
    cudaGetSymbolAddress((void**)&k2,   g_k2);
    cudaGetSymbolAddress((void**)&vt,   g_vt);
    cudaGetSymbolAddress((void**)&h,    g_h);

    cudaFuncSetAttribute(attn_hmma_kernel, cudaFuncAttributeMaxDynamicSharedMemorySize, ATTN_SMEM);
    cudaFuncSetAttribute(hmma_gemm_kernel, cudaFuncAttributeMaxDynamicSharedMemorySize, GEMM_SMEM);

    dim3 gemm_grid(MROWS / 128, HID / 128);      // (32, 16) = 512 CTAs, occ 2
    int nv4 = MROWS * HID / 4;

    WArgs wa;
    wa.src[0] = Wq; wa.dst[0] = Wq2;
    wa.src[1] = Wk; wa.dst[1] = Wk2;
    wa.src[2] = Wv; wa.dst[2] = Wv2;
    wa.src[3] = Wo; wa.dst[3] = Wo2;
    wa.src[4] = w1; wa.dst[4] = w12;
    wa.src[5] = w2; wa.dst[5] = w22;
    wa.src[6] = w3; wa.dst[6] = w32;

    rope_table_kernel<<<(SEQ * 64 + 255) / 256, 256>>>();
    wtrans_all_kernel<<<dim3(HID/64, HID/64, 7), 256>>>(wa);

    rmsnorm_h_kernel<<<MROWS, 256>>>(hs, ln1, xh);

    hmma_gemm_kernel<<<gemm_grid, 256, GEMM_SMEM>>>(xh, Wq2, nullptr, nullptr, qh);
    hmma_gemm_kernel<<<gemm_grid, 256, GEMM_SMEM>>>(xh, Wk2, nullptr, nullptr, kh);
    hmma_gemm_kernel<<<gemm_grid, 256, GEMM_SMEM>>>(xh, Wv2, nullptr, nullptr, vh);

    rope_h_kernel<<<MROWS, 256>>>(qh, kh, q2, k2);
    vconv_kernel<<<dim3(SEQ/32, HDIM/32, BATCH*NHEADS), 256>>>(vh, vt);

    attn_hmma_kernel<<<dim3(SEQ/128, NHEADS, BATCH), 256, ATTN_SMEM>>>(q2, k2, vt, ctxh);

    hmma_gemm_kernel<<<gemm_grid, 256, GEMM_SMEM>>>(ctxh, Wo2, hs, h, nullptr);  // h = hs + ctx@Wo

    rmsnorm_h_kernel<<<MROWS, 256>>>(h, ln2, xh);                                // y

    hmma_gemm_kernel<<<gemm_grid, 256, GEMM_SMEM>>>(xh, w12, nullptr, nullptr, g1h);
    hmma_gemm_kernel<<<gemm_grid, 256, GEMM_SMEM>>>(xh, w32, nullptr, nullptr, g3h);

    silu_h_kernel<<<(nv4 + 255) / 256, 256>>>(g1h, g3h, sx);

    hmma_gemm_kernel<<<gemm_grid, 256, GEMM_SMEM>>>(sx, w22, h, out, nullptr);   // out = h + mlp
}

// round 13
// speedup vs baseline: 1.0951x; 1.0201x over previous
#include <cuda_runtime.h>
#include <cuda_fp16.h>
#include <math.h>
#include <stdint.h>

// Problem constants
#define BATCH   2
#define SEQ     2048
#define HID     2048
#define NHEADS  16
#define HDIM    128
#define MROWS   (BATCH*SEQ)        // 4096
#define EPSV    1e-6f

// ---------------------------------------------------------------------------
// Scratch (__device__ globals; no cudaMalloc allowed)
// ---------------------------------------------------------------------------
__device__ __half g_xh   [MROWS*HID];          // rmsnorm out
__device__ __half g_ctxh [MROWS*HID];          // attention out
__device__ __half g_qkvh [(size_t)MROWS*3*HID];// packed q|k|v per token
__device__ __half g_g13h [(size_t)MROWS*2*HID];// packed g1|g3 per row
__device__ __half g_sx   [MROWS*HID];          // silu out
__device__ __half g_Wqkv [(size_t)3*HID*HID];  // [Wq^T ; Wk^T ; Wv^T]
__device__ __half g_Wo2  [HID*HID];
__device__ __half g_w13  [(size_t)2*HID*HID];  // [w1^T ; w3^T]
__device__ __half g_w22  [HID*HID];
__device__ float g_h  [MROWS*HID];
__device__ float g_cos[SEQ*64];
__device__ float g_sin[SEQ*64];
// attention operands (fp16, head-major)
__device__ __half g_q2 [(size_t)BATCH*NHEADS*SEQ*HDIM];  // [bh][s][128]
__device__ __half g_k2 [(size_t)BATCH*NHEADS*SEQ*HDIM];  // [bh][s][128]
__device__ __half g_vt [(size_t)BATCH*NHEADS*HDIM*SEQ];  // [bh][d][s]

// ---------------------------------------------------------------------------
// Helpers
// ---------------------------------------------------------------------------
__device__ __forceinline__ uint32_t smem_u32(const void* p) {
    uint32_t a;
    asm("{ .reg .u64 t; cvta.to.shared.u64 t, %1; cvt.u32.u64 %0, t; }" : "=r"(a) : "l"(p));
    return a;
}
__device__ __forceinline__ uint32_t packh(float x, float y) {
    __half2 t = __floats2half2_rn(x, y);
    return *(uint32_t*)&t;
}
__device__ __forceinline__ void cpasync16(uint32_t dst, const void* src) {
    asm volatile("cp.async.cg.shared.global [%0], [%1], 16;" :: "r"(dst), "l"(src));
}
__device__ __forceinline__ void ldm_x4(uint32_t& r0, uint32_t& r1, uint32_t& r2, uint32_t& r3,
                                       uint32_t addr) {
    asm volatile("ldmatrix.sync.aligned.m8n8.x4.shared.b16 {%0,%1,%2,%3}, [%4];"
                 : "=r"(r0), "=r"(r1), "=r"(r2), "=r"(r3) : "r"(addr));
}
__device__ __forceinline__ void mma16816h(float* c, const uint32_t* a, const uint32_t* b) {
    asm volatile(
        "mma.sync.aligned.m16n8k16.row.col.f32.f16.f16.f32 "
        "{%0,%1,%2,%3}, {%4,%5,%6,%7}, {%8,%9}, {%0,%1,%2,%3};"
        : "+f"(c[0]), "+f"(c[1]), "+f"(c[2]), "+f"(c[3])
        : "r"(a[0]), "r"(a[1]), "r"(a[2]), "r"(a[3]), "r"(b[0]), "r"(b[1]));
}

// ---------------------------------------------------------------------------
// RoPE cos/sin table
// ---------------------------------------------------------------------------
__global__ void rope_table_kernel() {
    int idx = blockIdx.x * 256 + threadIdx.x;
    if (idx < SEQ * 64) {
        int s = idx >> 6, i = idx & 63;
        double inv = pow(10000.0, -((double)(2 * i)) / 128.0);
        double ang = (double)s * inv;
        g_cos[idx] = (float)cos(ang);
        g_sin[idx] = (float)sin(ang);
    }
}

// ---------------------------------------------------------------------------
// RMSNorm -> fp16 (2048 wide)
// ---------------------------------------------------------------------------
__global__ __launch_bounds__(256) void rmsnorm_h_kernel(
    const float* __restrict__ x, const float* __restrict__ w, __half* __restrict__ outh)
{
    int row = blockIdx.x;
    const float4* xr = (const float4*)(x + (size_t)row * HID);
    float4 v0 = xr[threadIdx.x];
    float4 v1 = xr[threadIdx.x + 256];
    float ss = v0.x*v0.x + v0.y*v0.y + v0.z*v0.z + v0.w*v0.w
             + v1.x*v1.x + v1.y*v1.y + v1.z*v1.z + v1.w*v1.w;
    #pragma unroll
    for (int m = 16; m; m >>= 1) ss += __shfl_xor_sync(0xffffffffu, ss, m);
    __shared__ float red[8];
    if ((threadIdx.x & 31) == 0) red[threadIdx.x >> 5] = ss;
    __syncthreads();
    float tot = red[0] + red[1] + red[2] + red[3] + red[4] + red[5] + red[6] + red[7];
    float sc = rsqrtf(tot * (1.0f / (float)HID) + EPSV);
    const float4* wv = (const float4*)w;
    float4 w0 = wv[threadIdx.x];
    float4 w1v = wv[threadIdx.x + 256];
    __half* orow = outh + (size_t)row * HID;
    int c0 = threadIdx.x * 4, c1 = c0 + 1024;
    *(__half2*)&orow[c0]     = __floats2half2_rn(v0.x*sc*w0.x,  v0.y*sc*w0.y);
    *(__half2*)&orow[c0 + 2] = __floats2half2_rn(v0.z*sc*w0.z,  v0.w*sc*w0.w);
    *(__half2*)&orow[c1]     = __floats2half2_rn(v1.x*sc*w1v.x, v1.y*sc*w1v.y);
    *(__half2*)&orow[c1 + 2] = __floats2half2_rn(v1.z*sc*w1v.z, v1.w*sc*w1v.w);
}

// ---------------------------------------------------------------------------
// Batched weight transpose: 7x W[K][N] f32 -> B[N][K] fp16. 64x64 tiles.
// ---------------------------------------------------------------------------
struct WArgs { const float* src[7]; __half* dst[7]; };

__global__ __launch_bounds__(256) void wtrans_all_kernel(WArgs args) {
    const float* W = args.src[blockIdx.z];
    __half* B = args.dst[blockIdx.z];
    __shared__ float t[64][65];
    int bn = blockIdx.x * 64;   // n-tile
    int bk = blockIdx.y * 64;   // k-tile
    int tid = threadIdx.x;
    #pragma unroll
    for (int i = 0; i < 4; i++) {
        int idx = tid + 256*i;
        int r_ = idx >> 4, c4 = idx & 15;
        float4 vv = *(const float4*)(W + (size_t)(bk + r_) * HID + bn + c4*4);
        t[r_][c4*4+0] = vv.x; t[r_][c4*4+1] = vv.y;
        t[r_][c4*4+2] = vv.z; t[r_][c4*4+3] = vv.w;
    }
    __syncthreads();
    int n_ = tid >> 2, kc = (tid & 3) * 16;
    __half* orow = B + (size_t)(bn + n_) * HID + bk + kc;
    #pragma unroll
    for (int j = 0; j < 16; j += 2)
        *(__half2*)(orow + j) = __floats2half2_rn(t[kc + j][n_], t[kc + j + 1][n_]);
}

// ---------------------------------------------------------------------------
// HMMA fp16 GEMM: C[4096 x N] = A[4096 x 2048] @ B[N x 2048]^T (+Dd).
// Tile 128x128, BK=64, NSTG=2 (double-buffer, wait_group 1 — the pattern
// proven in the attention kernel). 8 warps, warp tile 64x32, occ 2.
// ldc: row stride of C/Ch/Dd. Output fp32 C (+Dd) or fp16 Ch.
// ---------------------------------------------------------------------------
#define ASTRIDE 72                           // 64 halves + 8 pad (144B rows)
#define OP_HALVES (128*ASTRIDE)              // 9216 per operand per stage
#define STGB ((OP_HALVES*2)*2)               // 36864 bytes
#define GEMM_SMEM (2*STGB)                   // 73728
#define KITERS (HID/64)                      // 32

__global__ __launch_bounds__(256, 2) void hmma_gemm_kernel(
    const __half* __restrict__ A, const __half* __restrict__ B,
    const float* __restrict__ Dd, float* __restrict__ C, __half* __restrict__ Ch,
    int ldc)
{
    extern __shared__ char smraw[];
    uint32_t smb = smem_u32(smraw);
    int tid = threadIdx.x, wid = tid >> 5, lid = tid & 31;
    int mt = blockIdx.x, nt = blockIdx.y;

    // load mapping: 4 A slots + 4 B slots per thread (1024 x 16B each operand)
    int row_ = tid >> 3;          // base row (advances by 32 per i)
    int seg  = tid & 7;           // 8-half segment within 64-half row
    const __half* aptr = A + (size_t)(mt*128 + row_) * HID + seg*8;
    const __half* bptr = B + (size_t)(nt*128 + row_) * HID + seg*8;
    uint32_t aoff = (uint32_t)(row_*ASTRIDE + seg*8) * 2;
    uint32_t boff = (uint32_t)(OP_HALVES + row_*ASTRIDE + seg*8) * 2;

    #define LOADIT(it_) do {                                             \
        uint32_t sb_ = smb + (uint32_t)((it_) & 1) * STGB;               \
        int k0_ = (it_) * 64;                                            \
        _Pragma("unroll")                                                \
        for (int i_ = 0; i_ < 4; i_++) {                                 \
            cpasync16(sb_ + aoff + (uint32_t)(i_*32*ASTRIDE)*2,          \
                      aptr + (size_t)(i_*32)*HID + k0_);                 \
            cpasync16(sb_ + boff + (uint32_t)(i_*32*ASTRIDE)*2,          \
                      bptr + (size_t)(i_*32)*HID + k0_);                 \
        }                                                                \
    } while (0)

    int m0w = (wid & 1) * 64, n0w = (wid >> 1) * 32;
    int g = lid >> 3, r = lid & 7;
    uint32_t aBaseH = (uint32_t)((m0w + r + (g & 1)*8) * ASTRIDE + (g >> 1)*8);
    uint32_t bBaseH = (uint32_t)(OP_HALVES + (n0w + r + (g >> 1)*8) * ASTRIDE + (g & 1)*8);

    float acc[4][4][4];
    #pragma unroll
    for (int mi = 0; mi < 4; mi++)
        #pragma unroll
        for (int ni = 0; ni < 4; ni++)
            #pragma unroll
            for (int e = 0; e < 4; e++) acc[mi][ni][e] = 0.0f;

    LOADIT(0);
    asm volatile("cp.async.commit_group;");
    LOADIT(1);
    asm volatile("cp.async.commit_group;");

    for (int it = 0; it < KITERS; it++) {
        asm volatile("cp.async.wait_group 1;");
        __syncthreads();
        uint32_t sb = smb + (uint32_t)(it & 1) * STGB;
        #pragma unroll
        for (int ks = 0; ks < 64; ks += 16) {
            uint32_t b[4][2];
            #pragma unroll
            for (int np = 0; np < 2; np++) {
                uint32_t r0, r1, r2, r3;
                ldm_x4(r0, r1, r2, r3, sb + 2*(bBaseH + (uint32_t)(np*16*ASTRIDE) + ks));
                b[np*2][0] = r0;   b[np*2][1] = r1;
                b[np*2+1][0] = r2; b[np*2+1][1] = r3;
            }
            #pragma unroll
            for (int mi = 0; mi < 4; mi++) {
                uint32_t a[4];
                ldm_x4(a[0], a[1], a[2], a[3], sb + 2*(aBaseH + (uint32_t)(mi*16*ASTRIDE) + ks));
                #pragma unroll
                for (int ni = 0; ni < 4; ni++) mma16816h(acc[mi][ni], a, b[ni]);
            }
        }
        __syncthreads();
        int itn = it + 2;
        if (itn < KITERS) LOADIT(itn);
        asm volatile("cp.async.commit_group;");
    }

    int lr = lid >> 2, lc = (lid & 3) * 2;
    #pragma unroll
    for (int mi = 0; mi < 4; mi++) {
        #pragma unroll
        for (int ni = 0; ni < 4; ni++) {
            int row0 = mt*128 + m0w + mi*16 + lr;
            int col  = nt*128 + n0w + ni*8 + lc;
            if (Ch) {
                *(__half2*)(Ch + (size_t)row0 * ldc + col) =
                    __floats2half2_rn(acc[mi][ni][0], acc[mi][ni][1]);
                *(__half2*)(Ch + (size_t)(row0 + 8) * ldc + col) =
                    __floats2half2_rn(acc[mi][ni][2], acc[mi][ni][3]);
            } else {
                float2 v0 = make_float2(acc[mi][ni][0], acc[mi][ni][1]);
                float2 v1 = make_float2(acc[mi][ni][2], acc[mi][ni][3]);
                if (Dd) {
                    float2 d0 = *(const float2*)(Dd + (size_t)row0 * ldc + col);
                    float2 d1 = *(const float2*)(Dd + (size_t)(row0 + 8) * ldc + col);
                    v0.x += d0.x; v0.y += d0.y;
                    v1.x += d1.x; v1.y += d1.y;
                }
                *(float2*)(C + (size_t)row0 * ldc + col)       = v0;
                *(float2*)(C + (size_t)(row0 + 8) * ldc + col) = v1;
            }
        }
    }
    #undef LOADIT
}

// ---------------------------------------------------------------------------
// RoPE + scale: packed qkv [token][6144] -> fp16 head-major q2,k2 [bh][s][128]
// ---------------------------------------------------------------------------
__global__ __launch_bounds__(256) void rope_h_kernel(
    const __half* __restrict__ qkv,
    __half* __restrict__ q2g, __half* __restrict__ k2g)
{
    int token = blockIdx.x;                  // b*SEQ + s
    int b = token >> 11, s = token & (SEQ-1);
    const __half* qr = qkv + (size_t)token * (3*HID);
    const __half* kr = qr + HID;
    const float qs = 0.08838834764831845f;   // 1/sqrt(128)
    for (int idx = threadIdx.x; idx < NHEADS*64; idx += 256) {
        int h = idx >> 6, i = idx & 63;
        float c  = g_cos[s*64 + i];
        float sn = g_sin[s*64 + i];
        float q1 = __half2float(qr[h*HDIM + i]), q2v = __half2float(qr[h*HDIM + i + 64]);
        float k1 = __half2float(kr[h*HDIM + i]), k2v = __half2float(kr[h*HDIM + i + 64]);
        __half* qd = q2g + ((size_t)(b*NHEADS + h)*SEQ + s) * HDIM;
        __half* kd = k2g + ((size_t)(b*NHEADS + h)*SEQ + s) * HDIM;
        qd[i]    = __float2half_rn((q1*c - q2v*sn) * qs);
        qd[i+64] = __float2half_rn((q2v*c + q1*sn) * qs);
        kd[i]    = __float2half_rn(k1*c - k2v*sn);
        kd[i+64] = __float2half_rn(k2v*c + k1*sn);
    }
}

// ---------------------------------------------------------------------------
// V transpose: packed qkv v-part [token][6144]+4096 -> fp16 vt[bh][d][s]
// ---------------------------------------------------------------------------
__global__ __launch_bounds__(256) void vconv_kernel(
    const __half* __restrict__ qkv, __half* __restrict__ vtg)
{
    __shared__ __half t[32][34];
    int s0 = blockIdx.x * 32, d0 = blockIdx.y * 32, bh = blockIdx.z;
    int b = bh >> 4, h = bh & 15;
    int tx = threadIdx.x & 31, ty = threadIdx.x >> 5;
    #pragma unroll
    for (int i = 0; i < 4; i++)
        t[ty + 8*i][tx] = qkv[(size_t)(b*SEQ + s0 + ty + 8*i) * (3*HID) + 2*HID + h*HDIM + d0 + tx];
    __syncthreads();
    __half* vb = vtg + (size_t)bh * HDIM * SEQ;
    #pragma unroll
    for (int i = 0; i < 4; i++) {
        int d = d0 + ty + 8*i;
        vb[(size_t)d*SEQ + s0 + tx] = t[tx][ty + 8*i];
    }
}

// ---------------------------------------------------------------------------
// HMMA flash attention, single-pass fp16 (proven in R7/R8/R12).
// ---------------------------------------------------------------------------
#define QS_STR 136
#define KS_STR 136
#define VS_STR 72
#define QS_OFF 0
#define KS_OFF (128*QS_STR)              // halves
#define KS_SZ  (64*KS_STR)
#define VS_OFF (KS_OFF + 2*KS_SZ)
#define VS_SZ  (128*VS_STR)
#define ATTN_SMEM ((VS_OFF + 2*VS_SZ)*2) // 106496 bytes

__global__ __launch_bounds__(256, 1) void attn_hmma_kernel(
    const __half* __restrict__ q2g, const __half* __restrict__ k2g,
    const __half* __restrict__ vtg, __half* __restrict__ ctxh)
{
    extern __shared__ char smraw[];
    uint32_t smb = smem_u32(smraw);
    int tid = threadIdx.x, wid = tid >> 5, lid = tid & 31;
    int qt = blockIdx.x, hh = blockIdx.y, b = blockIdx.z;
    int bh = b*NHEADS + hh;
    const __half* qbase = q2g + ((size_t)bh*SEQ + qt*128) * HDIM;
    const __half* kbase = k2g + (size_t)bh*SEQ * HDIM;
    const __half* vbase = vtg + (size_t)bh*HDIM*SEQ;

    #define LOAD_KT(st_, s0_) do {                                              \
        _Pragma("unroll")                                                       \
        for (int i_ = 0; i_ < 4; i_++) {                                        \
            int idx_ = tid + 256*i_; int row_ = idx_ >> 4, seg_ = idx_ & 15;    \
            cpasync16(smb + 2*(KS_OFF + (st_)*KS_SZ + row_*KS_STR + seg_*8),    \
                      kbase + ((size_t)((s0_) + row_))*HDIM + seg_*8);          \
        } } while (0)
    #define LOAD_VT(st_, s0_) do {                                              \
        _Pragma("unroll")                                                       \
        for (int i_ = 0; i_ < 4; i_++) {                                        \
            int idx_ = tid + 256*i_; int dr_ = idx_ >> 3, seg_ = idx_ & 7;      \
            cpasync16(smb + 2*(VS_OFF + (st_)*VS_SZ + dr_*VS_STR + seg_*8),     \
                      vbase + (size_t)dr_*SEQ + (s0_) + seg_*8);                \
        } } while (0)

    #pragma unroll
    for (int i = 0; i < 8; i++) {
        int idx = tid + 256*i; int row = idx >> 4, seg = idx & 15;
        cpasync16(smb + 2*(QS_OFF + row*QS_STR + seg*8),
                  qbase + (size_t)row*HDIM + seg*8);
    }
    LOAD_KT(0, 0); LOAD_VT(0, 0);
    asm volatile("cp.async.commit_group;");
    LOAD_KT(1, 64); LOAD_VT(1, 64);
    asm volatile("cp.async.commit_group;");

    int g = lid >> 3, r = lid & 7;
    uint32_t aQ = smb + 2*(QS_OFF + (uint32_t)((wid*16 + r + (g&1)*8)*QS_STR + (g>>1)*8));
    uint32_t bK = smb + 2*(KS_OFF + (uint32_t)((r + (g>>1)*8)*KS_STR + (g&1)*8));
    uint32_t bV = smb + 2*(VS_OFF + (uint32_t)((r + (g>>1)*8)*VS_STR + (g&1)*8));

    float oacc[16][4];
    #pragma unroll
    for (int n = 0; n < 16; n++)
        #pragma unroll
        for (int e = 0; e < 4; e++) oacc[n][e] = 0.0f;
    float m0 = -INFINITY, m1 = -INFINITY, l0 = 0.0f, l1 = 0.0f;

    for (int it = 0; it < SEQ/64; it++) {
        asm volatile("cp.async.wait_group 1;");
        __syncthreads();
        uint32_t kst = (uint32_t)((it & 1) * KS_SZ) * 2;
        uint32_t vst = (uint32_t)((it & 1) * VS_SZ) * 2;

        float sacc[8][4];
        #pragma unroll
        for (int n = 0; n < 8; n++)
            #pragma unroll
            for (int e = 0; e < 4; e++) sacc[n][e] = 0.0f;

        #pragma unroll
        for (int ks = 0; ks < 8; ks++) {
            uint32_t bfr[8][2];
            #pragma unroll
            for (int np = 0; np < 4; np++) {
                uint32_t r0,r1,r2,r3;
                ldm_x4(r0,r1,r2,r3, bK + kst + 2*(uint32_t)(np*16*KS_STR + ks*16));
                bfr[np*2][0]=r0; bfr[np*2][1]=r1; bfr[np*2+1][0]=r2; bfr[np*2+1][1]=r3;
            }
            uint32_t a[4];
            ldm_x4(a[0],a[1],a[2],a[3], aQ + 2*(uint32_t)(ks*16));
            #pragma unroll
            for (int n = 0; n < 8; n++) mma16816h(sacc[n], a, bfr[n]);
        }

        float mt0 = -INFINITY, mt1 = -INFINITY;
        #pragma unroll
        for (int n = 0; n < 8; n++) {
            mt0 = fmaxf(mt0, fmaxf(sacc[n][0], sacc[n][1]));
            mt1 = fmaxf(mt1, fmaxf(sacc[n][2], sacc[n][3]));
        }
        mt0 = fmaxf(mt0, __shfl_xor_sync(0xffffffffu, mt0, 1));
        mt0 = fmaxf(mt0, __shfl_xor_sync(0xffffffffu, mt0, 2));
        mt1 = fmaxf(mt1, __shfl_xor_sync(0xffffffffu, mt1, 1));
        mt1 = fmaxf(mt1, __shfl_xor_sync(0xffffffffu, mt1, 2));
        float mn0 = fmaxf(m0, mt0), mn1 = fmaxf(m1, mt1);
        float al0 = __expf(m0 - mn0), al1 = __expf(m1 - mn1);
        m0 = mn0; m1 = mn1;

        uint32_t ph0[8], ph1[8];
        float rs0 = 0.0f, rs1 = 0.0f;
        #pragma unroll
        for (int n = 0; n < 8; n++) {
            float p0 = __expf(sacc[n][0] - mn0);
            float p1 = __expf(sacc[n][1] - mn0);
            float p2 = __expf(sacc[n][2] - mn1);
            float p3 = __expf(sacc[n][3] - mn1);
            rs0 += p0 + p1; rs1 += p2 + p3;
            ph0[n] = packh(p0, p1);
            ph1[n] = packh(p2, p3);
        }
        rs0 += __shfl_xor_sync(0xffffffffu, rs0, 1);
        rs0 += __shfl_xor_sync(0xffffffffu, rs0, 2);
        rs1 += __shfl_xor_sync(0xffffffffu, rs1, 1);
        rs1 += __shfl_xor_sync(0xffffffffu, rs1, 2);
        l0 = l0*al0 + rs0; l1 = l1*al1 + rs1;
        #pragma unroll
        for (int n = 0; n < 16; n++) {
            oacc[n][0] *= al0; oacc[n][1] *= al0;
            oacc[n][2] *= al1; oacc[n][3] *= al1;
        }

        #pragma unroll
        for (int ks = 0; ks < 4; ks++) {
            uint32_t a[4] = { ph0[2*ks], ph1[2*ks], ph0[2*ks+1], ph1[2*ks+1] };
            #pragma unroll
            for (int np = 0; np < 8; np++) {
                uint32_t r0,r1,r2,r3;
                ldm_x4(r0,r1,r2,r3, bV + vst + 2*(uint32_t)(np*16*VS_STR + ks*16));
                uint32_t b0[2] = {r0, r1}, b1[2] = {r2, r3};
                mma16816h(oacc[np*2], a, b0); mma16816h(oacc[np*2+1], a, b1);
            }
        }

        __syncthreads();
        int itn = it + 2;
        if (itn < SEQ/64) {
            LOAD_KT(itn & 1, itn*64); LOAD_VT(itn & 1, itn*64);
        }
        asm volatile("cp.async.commit_group;");
    }

    float inv0 = 1.0f / l0, inv1 = 1.0f / l1;
    int row0 = qt*128 + wid*16 + (lid >> 2);
    int colb = 2*(lid & 3);
    __half* cb = ctxh + ((size_t)(b*SEQ) + row0) * HID + hh*HDIM;
    #pragma unroll
    for (int n = 0; n < 16; n++) {
        *(__half2*)(cb + n*8 + colb) =
            __floats2half2_rn(oacc[n][0]*inv0, oacc[n][1]*inv0);
        *(__half2*)(cb + (size_t)8*HID + n*8 + colb) =
            __floats2half2_rn(oacc[n][2]*inv1, oacc[n][3]*inv1);
    }
    #undef LOAD_KT
    #undef LOAD_VT
}

// ---------------------------------------------------------------------------
// silu(g1)*g3 from packed g13 [row][4096] -> fp16 sx [row][2048]
// ---------------------------------------------------------------------------
__global__ __launch_bounds__(256) void silu_h_kernel(
    const __half* __restrict__ g13, __half* __restrict__ outh)
{
    int i = blockIdx.x * 256 + threadIdx.x;  // group of 4 halves
    if (i >= MROWS * HID / 4) return;
    int row = i >> 9, col4 = i & 511;        // HID/4 = 512
    const __half* r1 = g13 + (size_t)row * (2*HID) + col4*4;
    const __half* r3 = r1 + HID;
    __half2 a0 = *(const __half2*)(r1),     a1 = *(const __half2*)(r1 + 2);
    __half2 b0 = *(const __half2*)(r3),     b1 = *(const __half2*)(r3 + 2);
    float ax = __low2float(a0), ay = __high2float(a0);
    float az = __low2float(a1), aw = __high2float(a1);
    float vx = (ax / (1.0f + expf(-ax))) * __low2float(b0);
    float vy = (ay / (1.0f + expf(-ay))) * __high2float(b0);
    float vz = (az / (1.0f + expf(-az))) * __low2float(b1);
    float vw = (aw / (1.0f + expf(-aw))) * __high2float(b1);
    __half2* o = (__half2*)(outh + (size_t)row * HID + col4*4);
    o[0] = __floats2half2_rn(vx, vy);
    o[1] = __floats2half2_rn(vz, vw);
}

// ---------------------------------------------------------------------------
// Launch
// ---------------------------------------------------------------------------
extern "C" void kernel_launch(void* const* d_in, const int* in_sizes, int n_in,
                              void* d_out, int out_size)
{
    (void)in_sizes; (void)n_in; (void)out_size;
    const float* hs  = (const float*)d_in[0];
    const float* Wq  = (const float*)d_in[1];
    const float* Wk  = (const float*)d_in[2];
    const float* Wv  = (const float*)d_in[3];
    const float* Wo  = (const float*)d_in[4];
    const float* w1  = (const float*)d_in[5];
    const float* w2  = (const float*)d_in[6];
    const float* w3  = (const float*)d_in[7];
    const float* ln1 = (const float*)d_in[8];
    const float* ln2 = (const float*)d_in[9];
    float* out = (float*)d_out;

    __half *xh, *ctxh, *qkvh, *g13h, *sx;
    __half *Wqkv, *Wo2, *w13, *w22;
    __half *q2, *k2, *vt;
    float *h;
    cudaGetSymbolAddress((void**)&xh,   g_xh);
    cudaGetSymbolAddress((void**)&ctxh, g_ctxh);
    cudaGetSymbolAddress((void**)&qkvh, g_qkvh);
    cudaGetSymbolAddress((void**)&g13h, g_g13h);
    cudaGetSymbolAddress((void**)&sx,   g_sx);
    cudaGetSymbolAddress((void**)&Wqkv, g_Wqkv);
    cudaGetSymbolAddress((void**)&Wo2,  g_Wo2);
    cudaGetSymbolAddress((void**)&w13,  g_w13);
    cudaGetSymbolAddress((void**)&w22,  g_w22);
    cudaGetSymbolAddress((void**)&q2,   g_q2);
    cudaGetSymbolAddress((void**)&k2,   g_k2);
    cudaGetSymbolAddress((void**)&vt,   g_vt);
    cudaGetSymbolAddress((void**)&h,    g_h);

    cudaFuncSetAttribute(attn_hmma_kernel, cudaFuncAttributeMaxDynamicSharedMemorySize, ATTN_SMEM);
    cudaFuncSetAttribute(hmma_gemm_kernel, cudaFuncAttributeMaxDynamicSharedMemorySize, GEMM_SMEM);

    int nv4 = MROWS * HID / 4;

    WArgs wa;
    wa.src[0] = Wq; wa.dst[0] = Wqkv;
    wa.src[1] = Wk; wa.dst[1] = Wqkv + (size_t)HID*HID;
    wa.src[2] = Wv; wa.dst[2] = Wqkv + (size_t)2*HID*HID;
    wa.src[3] = Wo; wa.dst[3] = Wo2;
    wa.src[4] = w1; wa.dst[4] = w13;
    wa.src[5] = w3; wa.dst[5] = w13 + (size_t)HID*HID;
    wa.src[6] = w2; wa.dst[6] = w22;

    rope_table_kernel<<<(SEQ * 64 + 255) / 256, 256>>>();
    wtrans_all_kernel<<<dim3(HID/64, HID/64, 7), 256>>>(wa);

    rmsnorm_h_kernel<<<MROWS, 256>>>(hs, ln1, xh);

    // QKV fused: N = 6144
    hmma_gemm_kernel<<<dim3(MROWS/128, 3*HID/128), 256, GEMM_SMEM>>>(
        xh, Wqkv, nullptr, nullptr, qkvh, 3*HID);

    rope_h_kernel<<<MROWS, 256>>>(qkvh, q2, k2);
    vconv_kernel<<<dim3(SEQ/32, HDIM/32, BATCH*NHEADS), 256>>>(qkvh, vt);

    attn_hmma_kernel<<<dim3(SEQ/128, NHEADS, BATCH), 256, ATTN_SMEM>>>(q2, k2, vt, ctxh);

    hmma_gemm_kernel<<<dim3(MROWS/128, HID/128), 256, GEMM_SMEM>>>(
        ctxh, Wo2, hs, h, nullptr, HID);                 // h = hs + ctx@Wo

    rmsnorm_h_kernel<<<MROWS, 256>>>(h, ln2, xh);        // y

    // w1 & w3 fused: N = 4096
    hmma_gemm_kernel<<<dim3(MROWS/128, 2*HID/128), 256, GEMM_SMEM>>>(
        xh, w13, nullptr, nullptr, g13h, 2*HID);

    silu_h_kernel<<<(nv4 + 255) / 256, 256>>>(g13h, sx);

    hmma_gemm_kernel<<<dim3(MROWS/128, HID/128), 256, GEMM_SMEM>>>(
        sx, w22, h, out, nullptr, HID);                  // out = h + mlp
}

// round 14
// speedup vs baseline: 1.1799x; 1.0775x over previous
#include <cuda_runtime.h>
#include <cuda_fp16.h>
#include <math.h>
#include <stdint.h>

// Problem constants
#define BATCH   2
#define SEQ     2048
#define HID     2048
#define NHEADS  16
#define HDIM    128
#define MROWS   (BATCH*SEQ)        // 4096
#define EPSV    1e-6f

// ---------------------------------------------------------------------------
// Scratch (__device__ globals; no cudaMalloc allowed)
// ---------------------------------------------------------------------------
__device__ __half g_xh   [MROWS*HID];          // rmsnorm out
__device__ __half g_ctxh [MROWS*HID];          // attention out
__device__ __half g_qkvh [(size_t)MROWS*3*HID];// packed q|k|v per token
__device__ __half g_g13h [(size_t)MROWS*2*HID];// packed g1|g3 per row
__device__ __half g_sx   [MROWS*HID];          // silu out
__device__ __half g_Wqkv [(size_t)3*HID*HID];  // [Wq^T ; Wk^T ; Wv^T]
__device__ __half g_Wo2  [HID*HID];
__device__ __half g_w13  [(size_t)2*HID*HID];  // [w1^T ; w3^T]
__device__ __half g_w22  [HID*HID];
__device__ float g_h  [MROWS*HID];
__device__ float g_cos[SEQ*64];
__device__ float g_sin[SEQ*64];
// attention operands (fp16, head-major)
__device__ __half g_q2 [(size_t)BATCH*NHEADS*SEQ*HDIM];  // [bh][s][128]
__device__ __half g_k2 [(size_t)BATCH*NHEADS*SEQ*HDIM];  // [bh][s][128]
__device__ __half g_vt [(size_t)BATCH*NHEADS*HDIM*SEQ];  // [bh][d][s]

// ---------------------------------------------------------------------------
// Helpers
// ---------------------------------------------------------------------------
__device__ __forceinline__ uint32_t smem_u32(const void* p) {
    uint32_t a;
    asm("{ .reg .u64 t; cvta.to.shared.u64 t, %1; cvt.u32.u64 %0, t; }" : "=r"(a) : "l"(p));
    return a;
}
__device__ __forceinline__ uint32_t packh(float x, float y) {
    __half2 t = __floats2half2_rn(x, y);
    return *(uint32_t*)&t;
}
__device__ __forceinline__ void cpasync16(uint32_t dst, const void* src) {
    asm volatile("cp.async.cg.shared.global [%0], [%1], 16;" :: "r"(dst), "l"(src));
}
__device__ __forceinline__ void ldm_x4(uint32_t& r0, uint32_t& r1, uint32_t& r2, uint32_t& r3,
                                       uint32_t addr) {
    asm volatile("ldmatrix.sync.aligned.m8n8.x4.shared.b16 {%0,%1,%2,%3}, [%4];"
                 : "=r"(r0), "=r"(r1), "=r"(r2), "=r"(r3) : "r"(addr));
}
__device__ __forceinline__ void mma16816h(float* c, const uint32_t* a, const uint32_t* b) {
    asm volatile(
        "mma.sync.aligned.m16n8k16.row.col.f32.f16.f16.f32 "
        "{%0,%1,%2,%3}, {%4,%5,%6,%7}, {%8,%9}, {%0,%1,%2,%3};"
        : "+f"(c[0]), "+f"(c[1]), "+f"(c[2]), "+f"(c[3])
        : "r"(a[0]), "r"(a[1]), "r"(a[2]), "r"(a[3]), "r"(b[0]), "r"(b[1]));
}

// ---------------------------------------------------------------------------
// RoPE cos/sin table
// ---------------------------------------------------------------------------
__global__ void rope_table_kernel() {
    int idx = blockIdx.x * 256 + threadIdx.x;
    if (idx < SEQ * 64) {
        int s = idx >> 6, i = idx & 63;
        double inv = pow(10000.0, -((double)(2 * i)) / 128.0);
        double ang = (double)s * inv;
        g_cos[idx] = (float)cos(ang);
        g_sin[idx] = (float)sin(ang);
    }
}

// ---------------------------------------------------------------------------
// RMSNorm -> fp16 (2048 wide)
// ---------------------------------------------------------------------------
__global__ __launch_bounds__(256) void rmsnorm_h_kernel(
    const float* __restrict__ x, const float* __restrict__ w, __half* __restrict__ outh)
{
    int row = blockIdx.x;
    const float4* xr = (const float4*)(x + (size_t)row * HID);
    float4 v0 = xr[threadIdx.x];
    float4 v1 = xr[threadIdx.x + 256];
    float ss = v0.x*v0.x + v0.y*v0.y + v0.z*v0.z + v0.w*v0.w
             + v1.x*v1.x + v1.y*v1.y + v1.z*v1.z + v1.w*v1.w;
    #pragma unroll
    for (int m = 16; m; m >>= 1) ss += __shfl_xor_sync(0xffffffffu, ss, m);
    __shared__ float red[8];
    if ((threadIdx.x & 31) == 0) red[threadIdx.x >> 5] = ss;
    __syncthreads();
    float tot = red[0] + red[1] + red[2] + red[3] + red[4] + red[5] + red[6] + red[7];
    float sc = rsqrtf(tot * (1.0f / (float)HID) + EPSV);
    const float4* wv = (const float4*)w;
    float4 w0 = wv[threadIdx.x];
    float4 w1v = wv[threadIdx.x + 256];
    __half* orow = outh + (size_t)row * HID;
    int c0 = threadIdx.x * 4, c1 = c0 + 1024;
    *(__half2*)&orow[c0]     = __floats2half2_rn(v0.x*sc*w0.x,  v0.y*sc*w0.y);
    *(__half2*)&orow[c0 + 2] = __floats2half2_rn(v0.z*sc*w0.z,  v0.w*sc*w0.w);
    *(__half2*)&orow[c1]     = __floats2half2_rn(v1.x*sc*w1v.x, v1.y*sc*w1v.y);
    *(__half2*)&orow[c1 + 2] = __floats2half2_rn(v1.z*sc*w1v.z, v1.w*sc*w1v.w);
}

// ---------------------------------------------------------------------------
// Batched weight transpose: 7x W[K][N] f32 -> B[N][K] fp16. 64x64 tiles.
// ---------------------------------------------------------------------------
struct WArgs { const float* src[7]; __half* dst[7]; };

__global__ __launch_bounds__(256) void wtrans_all_kernel(WArgs args) {
    const float* W = args.src[blockIdx.z];
    __half* B = args.dst[blockIdx.z];
    __shared__ float t[64][65];
    int bn = blockIdx.x * 64;   // n-tile
    int bk = blockIdx.y * 64;   // k-tile
    int tid = threadIdx.x;
    #pragma unroll
    for (int i = 0; i < 4; i++) {
        int idx = tid + 256*i;
        int r_ = idx >> 4, c4 = idx & 15;
        float4 vv = *(const float4*)(W + (size_t)(bk + r_) * HID + bn + c4*4);
        t[r_][c4*4+0] = vv.x; t[r_][c4*4+1] = vv.y;
        t[r_][c4*4+2] = vv.z; t[r_][c4*4+3] = vv.w;
    }
    __syncthreads();
    int n_ = tid >> 2, kc = (tid & 3) * 16;
    __half* orow = B + (size_t)(bn + n_) * HID + bk + kc;
    #pragma unroll
    for (int j = 0; j < 16; j += 2)
        *(__half2*)(orow + j) = __floats2half2_rn(t[kc + j][n_], t[kc + j + 1][n_]);
}

// ---------------------------------------------------------------------------
// HMMA fp16 GEMM: C[4096 x N] = A[4096 x 2048] @ B[N x 2048]^T (+Dd).
// Tile 128x128, BK=64, NSTG=3 (single barrier per iteration: with 3 stages
// the load for it+2 targets the stage consumed at it-1, which every warp
// finished before passing this iteration's barrier). 8 warps, warp tile
// 64x32, occ 2. ldc: row stride of C/Ch/Dd. fp32 C (+Dd) or fp16 Ch.
// ---------------------------------------------------------------------------
#define ASTRIDE 72                           // 64 halves + 8 pad (144B rows)
#define OP_HALVES (128*ASTRIDE)              // 9216 per operand per stage
#define STGB ((OP_HALVES*2)*2)               // 36864 bytes
#define NSTG 3
#define GEMM_SMEM (NSTG*STGB)                // 110592
#define KITERS (HID/64)                      // 32

__global__ __launch_bounds__(256, 2) void hmma_gemm_kernel(
    const __half* __restrict__ A, const __half* __restrict__ B,
    const float* __restrict__ Dd, float* __restrict__ C, __half* __restrict__ Ch,
    int ldc)
{
    extern __shared__ char smraw[];
    uint32_t smb = smem_u32(smraw);
    int tid = threadIdx.x, wid = tid >> 5, lid = tid & 31;
    int mt = blockIdx.x, nt = blockIdx.y;

    // load mapping: 4 A slots + 4 B slots per thread (1024 x 16B each operand)
    int row_ = tid >> 3;          // base row (advances by 32 per i)
    int seg  = tid & 7;           // 8-half segment within 64-half row
    const __half* aptr = A + (size_t)(mt*128 + row_) * HID + seg*8;
    const __half* bptr = B + (size_t)(nt*128 + row_) * HID + seg*8;
    uint32_t aoff = (uint32_t)(row_*ASTRIDE + seg*8) * 2;
    uint32_t boff = (uint32_t)(OP_HALVES + row_*ASTRIDE + seg*8) * 2;

    #define LOADIT(it_, st_) do {                                        \
        uint32_t sb_ = smb + (uint32_t)(st_) * STGB;                     \
        int k0_ = (it_) * 64;                                            \
        _Pragma("unroll")                                                \
        for (int i_ = 0; i_ < 4; i_++) {                                 \
            cpasync16(sb_ + aoff + (uint32_t)(i_*32*ASTRIDE)*2,          \
                      aptr + (size_t)(i_*32)*HID + k0_);                 \
            cpasync16(sb_ + boff + (uint32_t)(i_*32*ASTRIDE)*2,          \
                      bptr + (size_t)(i_*32)*HID + k0_);                 \
        }                                                                \
    } while (0)

    int m0w = (wid & 1) * 64, n0w = (wid >> 1) * 32;
    int g = lid >> 3, r = lid & 7;
    uint32_t aBaseH = (uint32_t)((m0w + r + (g & 1)*8) * ASTRIDE + (g >> 1)*8);
    uint32_t bBaseH = (uint32_t)(OP_HALVES + (n0w + r + (g >> 1)*8) * ASTRIDE + (g & 1)*8);

    float acc[4][4][4];
    #pragma unroll
    for (int mi = 0; mi < 4; mi++)
        #pragma unroll
        for (int ni = 0; ni < 4; ni++)
            #pragma unroll
            for (int e = 0; e < 4; e++) acc[mi][ni][e] = 0.0f;

    LOADIT(0, 0);
    asm volatile("cp.async.commit_group;");
    LOADIT(1, 1);
    asm volatile("cp.async.commit_group;");

    int scur = 0, sld = 2;   // stage of current iter; stage for it+2 loads
    for (int it = 0; it < KITERS; it++) {
        asm volatile("cp.async.wait_group 1;");
        __syncthreads();
        uint32_t sb = smb + (uint32_t)scur * STGB;
        #pragma unroll
        for (int ks = 0; ks < 64; ks += 16) {
            uint32_t b[4][2];
            #pragma unroll
            for (int np = 0; np < 2; np++) {
                uint32_t r0, r1, r2, r3;
                ldm_x4(r0, r1, r2, r3, sb + 2*(bBaseH + (uint32_t)(np*16*ASTRIDE) + ks));
                b[np*2][0] = r0;   b[np*2][1] = r1;
                b[np*2+1][0] = r2; b[np*2+1][1] = r3;
            }
            #pragma unroll
            for (int mi = 0; mi < 4; mi++) {
                uint32_t a[4];
                ldm_x4(a[0], a[1], a[2], a[3], sb + 2*(aBaseH + (uint32_t)(mi*16*ASTRIDE) + ks));
                #pragma unroll
                for (int ni = 0; ni < 4; ni++) mma16816h(acc[mi][ni], a, b[ni]);
            }
        }
        int itn = it + 2;
        if (itn < KITERS) LOADIT(itn, sld);
        asm volatile("cp.async.commit_group;");
        scur = (scur == 2) ? 0 : scur + 1;
        sld  = (sld  == 2) ? 0 : sld  + 1;
    }

    int lr = lid >> 2, lc = (lid & 3) * 2;
    #pragma unroll
    for (int mi = 0; mi < 4; mi++) {
        #pragma unroll
        for (int ni = 0; ni < 4; ni++) {
            int row0 = mt*128 + m0w + mi*16 + lr;
            int col  = nt*128 + n0w + ni*8 + lc;
            if (Ch) {
                *(__half2*)(Ch + (size_t)row0 * ldc + col) =
                    __floats2half2_rn(acc[mi][ni][0], acc[mi][ni][1]);
                *(__half2*)(Ch + (size_t)(row0 + 8) * ldc + col) =
                    __floats2half2_rn(acc[mi][ni][2], acc[mi][ni][3]);
            } else {
                float2 v0 = make_float2(acc[mi][ni][0], acc[mi][ni][1]);
                float2 v1 = make_float2(acc[mi][ni][2], acc[mi][ni][3]);
                if (Dd) {
                    float2 d0 = *(const float2*)(Dd + (size_t)row0 * ldc + col);
                    float2 d1 = *(const float2*)(Dd + (size_t)(row0 + 8) * ldc + col);
                    v0.x += d0.x; v0.y += d0.y;
                    v1.x += d1.x; v1.y += d1.y;
                }
                *(float2*)(C + (size_t)row0 * ldc + col)       = v0;
                *(float2*)(C + (size_t)(row0 + 8) * ldc + col) = v1;
            }
        }
    }
    #undef LOADIT
}

// ---------------------------------------------------------------------------
// RoPE + scale: packed qkv [token][6144] -> fp16 head-major q2,k2 [bh][s][128]
// ---------------------------------------------------------------------------
__global__ __launch_bounds__(256) void rope_h_kernel(
    const __half* __restrict__ qkv,
    __half* __restrict__ q2g, __half* __restrict__ k2g)
{
    int token = blockIdx.x;                  // b*SEQ + s
    int b = token >> 11, s = token & (SEQ-1);
    const __half* qr = qkv + (size_t)token * (3*HID);
    const __half* kr = qr + HID;
    const float qs = 0.08838834764831845f;   // 1/sqrt(128)
    for (int idx = threadIdx.x; idx < NHEADS*64; idx += 256) {
        int h = idx >> 6, i = idx & 63;
        float c  = g_cos[s*64 + i];
        float sn = g_sin[s*64 + i];
        float q1 = __half2float(qr[h*HDIM + i]), q2v = __half2float(qr[h*HDIM + i + 64]);
        float k1 = __half2float(kr[h*HDIM + i]), k2v = __half2float(kr[h*HDIM + i + 64]);
        __half* qd = q2g + ((size_t)(b*NHEADS + h)*SEQ + s) * HDIM;
        __half* kd = k2g + ((size_t)(b*NHEADS + h)*SEQ + s) * HDIM;
        qd[i]    = __float2half_rn((q1*c - q2v*sn) * qs);
        qd[i+64] = __float2half_rn((q2v*c + q1*sn) * qs);
        kd[i]    = __float2half_rn(k1*c - k2v*sn);
        kd[i+64] = __float2half_rn(k2v*c + k1*sn);
    }
}

// ---------------------------------------------------------------------------
// V transpose: packed qkv v-part -> fp16 vt[bh][d][s]
// ---------------------------------------------------------------------------
__global__ __launch_bounds__(256) void vconv_kernel(
    const __half* __restrict__ qkv, __half* __restrict__ vtg)
{
    __shared__ __half t[32][34];
    int s0 = blockIdx.x * 32, d0 = blockIdx.y * 32, bh = blockIdx.z;
    int b = bh >> 4, h = bh & 15;
    int tx = threadIdx.x & 31, ty = threadIdx.x >> 5;
    #pragma unroll
    for (int i = 0; i < 4; i++)
        t[ty + 8*i][tx] = qkv[(size_t)(b*SEQ + s0 + ty + 8*i) * (3*HID) + 2*HID + h*HDIM + d0 + tx];
    __syncthreads();
    __half* vb = vtg + (size_t)bh * HDIM * SEQ;
    #pragma unroll
    for (int i = 0; i < 4; i++) {
        int d = d0 + ty + 8*i;
        vb[(size_t)d*SEQ + s0 + tx] = t[tx][ty + 8*i];
    }
}

// ---------------------------------------------------------------------------
// HMMA flash attention, single-pass fp16 (proven R7/R8/R12/R13); occ 2 now.
// ---------------------------------------------------------------------------
#define QS_STR 136
#define KS_STR 136
#define VS_STR 72
#define QS_OFF 0
#define KS_OFF (128*QS_STR)              // halves
#define KS_SZ  (64*KS_STR)
#define VS_OFF (KS_OFF + 2*KS_SZ)
#define VS_SZ  (128*VS_STR)
#define ATTN_SMEM ((VS_OFF + 2*VS_SZ)*2) // 106496 bytes

__global__ __launch_bounds__(256, 2) void attn_hmma_kernel(
    const __half* __restrict__ q2g, const __half* __restrict__ k2g,
    const __half* __restrict__ vtg, __half* __restrict__ ctxh)
{
    extern __shared__ char smraw[];
    uint32_t smb = smem_u32(smraw);
    int tid = threadIdx.x, wid = tid >> 5, lid = tid & 31;
    int qt = blockIdx.x, hh = blockIdx.y, b = blockIdx.z;
    int bh = b*NHEADS + hh;
    const __half* qbase = q2g + ((size_t)bh*SEQ + qt*128) * HDIM;
    const __half* kbase = k2g + (size_t)bh*SEQ * HDIM;
    const __half* vbase = vtg + (size_t)bh*HDIM*SEQ;

    #define LOAD_KT(st_, s0_) do {                                              \
        _Pragma("unroll")                                                       \
        for (int i_ = 0; i_ < 4; i_++) {                                        \
            int idx_ = tid + 256*i_; int row_ = idx_ >> 4, seg_ = idx_ & 15;    \
            cpasync16(smb + 2*(KS_OFF + (st_)*KS_SZ + row_*KS_STR + seg_*8),    \
                      kbase + ((size_t)((s0_) + row_))*HDIM + seg_*8);          \
        } } while (0)
    #define LOAD_VT(st_, s0_) do {                                              \
        _Pragma("unroll")                                                       \
        for (int i_ = 0; i_ < 4; i_++) {                                        \
            int idx_ = tid + 256*i_; int dr_ = idx_ >> 3, seg_ = idx_ & 7;      \
            cpasync16(smb + 2*(VS_OFF + (st_)*VS_SZ + dr_*VS_STR + seg_*8),     \
                      vbase + (size_t)dr_*SEQ + (s0_) + seg_*8);                \
        } } while (0)

    #pragma unroll
    for (int i = 0; i < 8; i++) {
        int idx = tid + 256*i; int row = idx >> 4, seg = idx & 15;
        cpasync16(smb + 2*(QS_OFF + row*QS_STR + seg*8),
                  qbase + (size_t)row*HDIM + seg*8);
    }
    LOAD_KT(0, 0); LOAD_VT(0, 0);
    asm volatile("cp.async.commit_group;");
    LOAD_KT(1, 64); LOAD_VT(1, 64);
    asm volatile("cp.async.commit_group;");

    int g = lid >> 3, r = lid & 7;
    uint32_t aQ = smb + 2*(QS_OFF + (uint32_t)((wid*16 + r + (g&1)*8)*QS_STR + (g>>1)*8));
    uint32_t bK = smb + 2*(KS_OFF + (uint32_t)((r + (g>>1)*8)*KS_STR + (g&1)*8));
    uint32_t bV = smb + 2*(VS_OFF + (uint32_t)((r + (g>>1)*8)*VS_STR + (g&1)*8));

    float oacc[16][4];
    #pragma unroll
    for (int n = 0; n < 16; n++)
        #pragma unroll
        for (int e = 0; e < 4; e++) oacc[n][e] = 0.0f;
    float m0 = -INFINITY, m1 = -INFINITY, l0 = 0.0f, l1 = 0.0f;

    for (int it = 0; it < SEQ/64; it++) {
        asm volatile("cp.async.wait_group 1;");
        __syncthreads();
        uint32_t kst = (uint32_t)((it & 1) * KS_SZ) * 2;
        uint32_t vst = (uint32_t)((it & 1) * VS_SZ) * 2;

        float sacc[8][4];
        #pragma unroll
        for (int n = 0; n < 8; n++)
            #pragma unroll
            for (int e = 0; e < 4; e++) sacc[n][e] = 0.0f;

        #pragma unroll
        for (int ks = 0; ks < 8; ks++) {
            uint32_t bfr[8][2];
            #pragma unroll
            for (int np = 0; np < 4; np++) {
                uint32_t r0,r1,r2,r3;
                ldm_x4(r0,r1,r2,r3, bK + kst + 2*(uint32_t)(np*16*KS_STR + ks*16));
                bfr[np*2][0]=r0; bfr[np*2][1]=r1; bfr[np*2+1][0]=r2; bfr[np*2+1][1]=r3;
            }
            uint32_t a[4];
            ldm_x4(a[0],a[1],a[2],a[3], aQ + 2*(uint32_t)(ks*16));
            #pragma unroll
            for (int n = 0; n < 8; n++) mma16816h(sacc[n], a, bfr[n]);
        }

        float mt0 = -INFINITY, mt1 = -INFINITY;
        #pragma unroll
        for (int n = 0; n < 8; n++) {
            mt0 = fmaxf(mt0, fmaxf(sacc[n][0], sacc[n][1]));
            mt1 = fmaxf(mt1, fmaxf(sacc[n][2], sacc[n][3]));
        }
        mt0 = fmaxf(mt0, __shfl_xor_sync(0xffffffffu, mt0, 1));
        mt0 = fmaxf(mt0, __shfl_xor_sync(0xffffffffu, mt0, 2));
        mt1 = fmaxf(mt1, __shfl_xor_sync(0xffffffffu, mt1, 1));
        mt1 = fmaxf(mt1, __shfl_xor_sync(0xffffffffu, mt1, 2));
        float mn0 = fmaxf(m0, mt0), mn1 = fmaxf(m1, mt1);
        float al0 = __expf(m0 - mn0), al1 = __expf(m1 - mn1);
        m0 = mn0; m1 = mn1;

        uint32_t ph0[8], ph1[8];
        float rs0 = 0.0f, rs1 = 0.0f;
        #pragma unroll
        for (int n = 0; n < 8; n++) {
            float p0 = __expf(sacc[n][0] - mn0);
            float p1 = __expf(sacc[n][1] - mn0);
            float p2 = __expf(sacc[n][2] - mn1);
            float p3 = __expf(sacc[n][3] - mn1);
            rs0 += p0 + p1; rs1 += p2 + p3;
            ph0[n] = packh(p0, p1);
            ph1[n] = packh(p2, p3);
        }
        rs0 += __shfl_xor_sync(0xffffffffu, rs0, 1);
        rs0 += __shfl_xor_sync(0xffffffffu, rs0, 2);
        rs1 += __shfl_xor_sync(0xffffffffu, rs1, 1);
        rs1 += __shfl_xor_sync(0xffffffffu, rs1, 2);
        l0 = l0*al0 + rs0; l1 = l1*al1 + rs1;
        #pragma unroll
        for (int n = 0; n < 16; n++) {
            oacc[n][0] *= al0; oacc[n][1] *= al0;
            oacc[n][2] *= al1; oacc[n][3] *= al1;
        }

        #pragma unroll
        for (int ks = 0; ks < 4; ks++) {
            uint32_t a[4] = { ph0[2*ks], ph1[2*ks], ph0[2*ks+1], ph1[2*ks+1] };
            #pragma unroll
            for (int np = 0; np < 8; np++) {
                uint32_t r0,r1,r2,r3;
                ldm_x4(r0,r1,r2,r3, bV + vst + 2*(uint32_t)(np*16*VS_STR + ks*16));
                uint32_t b0[2] = {r0, r1}, b1[2] = {r2, r3};
                mma16816h(oacc[np*2], a, b0); mma16816h(oacc[np*2+1], a, b1);
            }
        }

        __syncthreads();
        int itn = it + 2;
        if (itn < SEQ/64) {
            LOAD_KT(itn & 1, itn*64); LOAD_VT(itn & 1, itn*64);
        }
        asm volatile("cp.async.commit_group;");
    }

    float inv0 = 1.0f / l0, inv1 = 1.0f / l1;
    int row0 = qt*128 + wid*16 + (lid >> 2);
    int colb = 2*(lid & 3);
    __half* cb = ctxh + ((size_t)(b*SEQ) + row0) * HID + hh*HDIM;
    #pragma unroll
    for (int n = 0; n < 16; n++) {
        *(__half2*)(cb + n*8 + colb) =
            __floats2half2_rn(oacc[n][0]*inv0, oacc[n][1]*inv0);
        *(__half2*)(cb + (size_t)8*HID + n*8 + colb) =
            __floats2half2_rn(oacc[n][2]*inv1, oacc[n][3]*inv1);
    }
    #undef LOAD_KT
    #undef LOAD_VT
}

// ---------------------------------------------------------------------------
// silu(g1)*g3 from packed g13 [row][4096] -> fp16 sx [row][2048]
// ---------------------------------------------------------------------------
__global__ __launch_bounds__(256) void silu_h_kernel(
    const __half* __restrict__ g13, __half* __restrict__ outh)
{
    int i = blockIdx.x * 256 + threadIdx.x;  // group of 4 halves
    if (i >= MROWS * HID / 4) return;
    int row = i >> 9, col4 = i & 511;        // HID/4 = 512
    const __half* r1 = g13 + (size_t)row * (2*HID) + col4*4;
    const __half* r3 = r1 + HID;
    __half2 a0 = *(const __half2*)(r1),     a1 = *(const __half2*)(r1 + 2);
    __half2 b0 = *(const __half2*)(r3),     b1 = *(const __half2*)(r3 + 2);
    float ax = __low2float(a0), ay = __high2float(a0);
    float az = __low2float(a1), aw = __high2float(a1);
    float vx = (ax / (1.0f + expf(-ax))) * __low2float(b0);
    float vy = (ay / (1.0f + expf(-ay))) * __high2float(b0);
    float vz = (az / (1.0f + expf(-az))) * __low2float(b1);
    float vw = (aw / (1.0f + expf(-aw))) * __high2float(b1);
    __half2* o = (__half2*)(outh + (size_t)row * HID + col4*4);
    o[0] = __floats2half2_rn(vx, vy);
    o[1] = __floats2half2_rn(vz, vw);
}

// ---------------------------------------------------------------------------
// Launch
// ---------------------------------------------------------------------------
extern "C" void kernel_launch(void* const* d_in, const int* in_sizes, int n_in,
                              void* d_out, int out_size)
{
    (void)in_sizes; (void)n_in; (void)out_size;
    const float* hs  = (const float*)d_in[0];
    const float* Wq  = (const float*)d_in[1];
    const float* Wk  = (const float*)d_in[2];
    const float* Wv  = (const float*)d_in[3];
    const float* Wo  = (const float*)d_in[4];
    const float* w1  = (const float*)d_in[5];
    const float* w2  = (const float*)d_in[6];
    const float* w3  = (const float*)d_in[7];
    const float* ln1 = (const float*)d_in[8];
    const float* ln2 = (const float*)d_in[9];
    float* out = (float*)d_out;

    __half *xh, *ctxh, *qkvh, *g13h, *sx;
    __half *Wqkv, *Wo2, *w13, *w22;
    __half *q2, *k2, *vt;
    float *h;
    cudaGetSymbolAddress((void**)&xh,   g_xh);
    cudaGetSymbolAddress((void**)&ctxh, g_ctxh);
    cudaGetSymbolAddress((void**)&qkvh, g_qkvh);
    cudaGetSymbolAddress((void**)&g13h, g_g13h);
    cudaGetSymbolAddress((void**)&sx,   g_sx);
    cudaGetSymbolAddress((void**)&Wqkv, g_Wqkv);
    cudaGetSymbolAddress((void**)&Wo2,  g_Wo2);
    cudaGetSymbolAddress((void**)&w13,  g_w13);
    cudaGetSymbolAddress((void**)&w22,  g_w22);
    cudaGetSymbolAddress((void**)&q2,   g_q2);
    cudaGetSymbolAddress((void**)&k2,   g_k2);
    cudaGetSymbolAddress((void**)&vt,   g_vt);
    cudaGetSymbolAddress((void**)&h,    g_h);

    cudaFuncSetAttribute(attn_hmma_kernel, cudaFuncAttributeMaxDynamicSharedMemorySize, ATTN_SMEM);
    cudaFuncSetAttribute(hmma_gemm_kernel, cudaFuncAttributeMaxDynamicSharedMemorySize, GEMM_SMEM);

    int nv4 = MROWS * HID / 4;

    WArgs wa;
    wa.src[0] = Wq; wa.dst[0] = Wqkv;
    wa.src[1] = Wk; wa.dst[1] = Wqkv + (size_t)HID*HID;
    wa.src[2] = Wv; wa.dst[2] = Wqkv + (size_t)2*HID*HID;
    wa.src[3] = Wo; wa.dst[3] = Wo2;
    wa.src[4] = w1; wa.dst[4] = w13;
    wa.src[5] = w3; wa.dst[5] = w13 + (size_t)HID*HID;
    wa.src[6] = w2; wa.dst[6] = w22;

    rope_table_kernel<<<(SEQ * 64 + 255) / 256, 256>>>();
    wtrans_all_kernel<<<dim3(HID/64, HID/64, 7), 256>>>(wa);

    rmsnorm_h_kernel<<<MROWS, 256>>>(hs, ln1, xh);

    // QKV fused: N = 6144
    hmma_gemm_kernel<<<dim3(MROWS/128, 3*HID/128), 256, GEMM_SMEM>>>(
        xh, Wqkv, nullptr, nullptr, qkvh, 3*HID);

    rope_h_kernel<<<MROWS, 256>>>(qkvh, q2, k2);
    vconv_kernel<<<dim3(SEQ/32, HDIM/32, BATCH*NHEADS), 256>>>(qkvh, vt);

    attn_hmma_kernel<<<dim3(SEQ/128, NHEADS, BATCH), 256, ATTN_SMEM>>>(q2, k2, vt, ctxh);

    hmma_gemm_kernel<<<dim3(MROWS/128, HID/128), 256, GEMM_SMEM>>>(
        ctxh, Wo2, hs, h, nullptr, HID);                 // h = hs + ctx@Wo

    rmsnorm_h_kernel<<<MROWS, 256>>>(h, ln2, xh);        // y

    // w1 & w3 fused: N = 4096
    hmma_gemm_kernel<<<dim3(MROWS/128, 2*HID/128), 256, GEMM_SMEM>>>(
        xh, w13, nullptr, nullptr, g13h, 2*HID);

    silu_h_kernel<<<(nv4 + 255) / 256, 256>>>(g13h, sx);

    hmma_gemm_kernel<<<dim3(MROWS/128, HID/128), 256, GEMM_SMEM>>>(
        sx, w22, h, out, nullptr, HID);                  // out = h + mlp
}

// round 15
// speedup vs baseline: 1.2509x; 1.0601x over previous
#include <cuda_runtime.h>
#include <cuda_fp16.h>
#include <math.h>
#include <stdint.h>

// Problem constants
#define BATCH   2
#define SEQ     2048
#define HID     2048
#define NHEADS  16
#define HDIM    128
#define MROWS   (BATCH*SEQ)        // 4096
#define EPSV    1e-6f

// ---------------------------------------------------------------------------
// Scratch (__device__ globals; no cudaMalloc allowed)
// ---------------------------------------------------------------------------
__device__ __half g_xh   [MROWS*HID];          // rmsnorm out
__device__ __half g_ctxh [MROWS*HID];          // attention out
__device__ __half g_sx   [MROWS*HID];          // silu out (w2 GEMM input)
__device__ __half g_Wqkv [(size_t)3*HID*HID];  // [Wq^T ; Wk^T ; Wv^T]
__device__ __half g_Wo2  [HID*HID];
__device__ __half g_w13  [(size_t)2*HID*HID];  // row-interleaved [w1_j ; w3_j]
__device__ __half g_w22  [HID*HID];
__device__ float g_h  [MROWS*HID];
__device__ float g_cos[SEQ*64];
__device__ float g_sin[SEQ*64];
// attention operands (fp16, head-major)
__device__ __half g_q2 [(size_t)BATCH*NHEADS*SEQ*HDIM];  // [bh][s][128]
__device__ __half g_k2 [(size_t)BATCH*NHEADS*SEQ*HDIM];  // [bh][s][128]
__device__ __half g_vt [(size_t)BATCH*NHEADS*HDIM*SEQ];  // [bh][d][s]

// ---------------------------------------------------------------------------
// Helpers
// ---------------------------------------------------------------------------
__device__ __forceinline__ uint32_t smem_u32(const void* p) {
    uint32_t a;
    asm("{ .reg .u64 t; cvta.to.shared.u64 t, %1; cvt.u32.u64 %0, t; }" : "=r"(a) : "l"(p));
    return a;
}
__device__ __forceinline__ uint32_t packh(float x, float y) {
    __half2 t = __floats2half2_rn(x, y);
    return *(uint32_t*)&t;
}
__device__ __forceinline__ void cpasync16(uint32_t dst, const void* src) {
    asm volatile("cp.async.cg.shared.global [%0], [%1], 16;" :: "r"(dst), "l"(src));
}
__device__ __forceinline__ void ldm_x4(uint32_t& r0, uint32_t& r1, uint32_t& r2, uint32_t& r3,
                                       uint32_t addr) {
    asm volatile("ldmatrix.sync.aligned.m8n8.x4.shared.b16 {%0,%1,%2,%3}, [%4];"
                 : "=r"(r0), "=r"(r1), "=r"(r2), "=r"(r3) : "r"(addr));
}
__device__ __forceinline__ void mma16816h(float* c, const uint32_t* a, const uint32_t* b) {
    asm volatile(
        "mma.sync.aligned.m16n8k16.row.col.f32.f16.f16.f32 "
        "{%0,%1,%2,%3}, {%4,%5,%6,%7}, {%8,%9}, {%0,%1,%2,%3};"
        : "+f"(c[0]), "+f"(c[1]), "+f"(c[2]), "+f"(c[3])
        : "r"(a[0]), "r"(a[1]), "r"(a[2]), "r"(a[3]), "r"(b[0]), "r"(b[1]));
}

// ---------------------------------------------------------------------------
// RoPE cos/sin table
// ---------------------------------------------------------------------------
__global__ void rope_table_kernel() {
    int idx = blockIdx.x * 256 + threadIdx.x;
    if (idx < SEQ * 64) {
        int s = idx >> 6, i = idx & 63;
        double inv = pow(10000.0, -((double)(2 * i)) / 128.0);
        double ang = (double)s * inv;
        g_cos[idx] = (float)cos(ang);
        g_sin[idx] = (float)sin(ang);
    }
}

// ---------------------------------------------------------------------------
// RMSNorm -> fp16 (2048 wide)
// ---------------------------------------------------------------------------
__global__ __launch_bounds__(256) void rmsnorm_h_kernel(
    const float* __restrict__ x, const float* __restrict__ w, __half* __restrict__ outh)
{
    int row = blockIdx.x;
    const float4* xr = (const float4*)(x + (size_t)row * HID);
    float4 v0 = xr[threadIdx.x];
    float4 v1 = xr[threadIdx.x + 256];
    float ss = v0.x*v0.x + v0.y*v0.y + v0.z*v0.z + v0.w*v0.w
             + v1.x*v1.x + v1.y*v1.y + v1.z*v1.z + v1.w*v1.w;
    #pragma unroll
    for (int m = 16; m; m >>= 1) ss += __shfl_xor_sync(0xffffffffu, ss, m);
    __shared__ float red[8];
    if ((threadIdx.x & 31) == 0) red[threadIdx.x >> 5] = ss;
    __syncthreads();
    float tot = red[0] + red[1] + red[2] + red[3] + red[4] + red[5] + red[6] + red[7];
    float sc = rsqrtf(tot * (1.0f / (float)HID) + EPSV);
    const float4* wv = (const float4*)w;
    float4 w0 = wv[threadIdx.x];
    float4 w1v = wv[threadIdx.x + 256];
    __half* orow = outh + (size_t)row * HID;
    int c0 = threadIdx.x * 4, c1 = c0 + 1024;
    *(__half2*)&orow[c0]     = __floats2half2_rn(v0.x*sc*w0.x,  v0.y*sc*w0.y);
    *(__half2*)&orow[c0 + 2] = __floats2half2_rn(v0.z*sc*w0.z,  v0.w*sc*w0.w);
    *(__half2*)&orow[c1]     = __floats2half2_rn(v1.x*sc*w1v.x, v1.y*sc*w1v.y);
    *(__half2*)&orow[c1 + 2] = __floats2half2_rn(v1.z*sc*w1v.z, v1.w*sc*w1v.w);
}

// ---------------------------------------------------------------------------
// Batched weight transpose: 7x W[K][N] f32 -> B fp16 with per-slot row
// interleave: dst row = n*rs + ro (rs=2,ro=0/1 packs w1/w3 interleaved).
// ---------------------------------------------------------------------------
struct WArgs { const float* src[7]; __half* dst[7]; int rs[7]; int ro[7]; };

__global__ __launch_bounds__(256) void wtrans_all_kernel(WArgs args) {
    const float* W = args.src[blockIdx.z];
    __half* B = args.dst[blockIdx.z];
    int rs = args.rs[blockIdx.z], ro = args.ro[blockIdx.z];
    __shared__ float t[64][65];
    int bn = blockIdx.x * 64;   // n-tile
    int bk = blockIdx.y * 64;   // k-tile
    int tid = threadIdx.x;
    #pragma unroll
    for (int i = 0; i < 4; i++) {
        int idx = tid + 256*i;
        int r_ = idx >> 4, c4 = idx & 15;
        float4 vv = *(const float4*)(W + (size_t)(bk + r_) * HID + bn + c4*4);
        t[r_][c4*4+0] = vv.x; t[r_][c4*4+1] = vv.y;
        t[r_][c4*4+2] = vv.z; t[r_][c4*4+3] = vv.w;
    }
    __syncthreads();
    int n_ = tid >> 2, kc = (tid & 3) * 16;
    __half* orow = B + ((size_t)(bn + n_) * rs + ro) * HID + bk + kc;
    #pragma unroll
    for (int j = 0; j < 16; j += 2)
        *(__half2*)(orow + j) = __floats2half2_rn(t[kc + j][n_], t[kc + j + 1][n_]);
}

// ---------------------------------------------------------------------------
// HMMA fp16 GEMM: C[4096 x N] = A[4096 x 2048] @ B[N x 2048]^T.
// Tile 128x128, BK=64, NSTG=3, single barrier/iter, occ 2.
// mode 0: fp32 C (+Dd residual), ldc stride.
// mode 2: QKV epilogue — rope + head-major scatter to g_q2/g_k2, V transpose
//         to g_vt (N must be 6144; tiles: nt<16 q-head, <32 k-head, else v).
// mode 3: silu epilogue — cols are interleaved (g1,g3) pairs; writes
//         silu(g1)*g3 fp16 to Ch [4096 x 2048].
// ---------------------------------------------------------------------------
#define ASTRIDE 72                           // 64 halves + 8 pad (144B rows)
#define OP_HALVES (128*ASTRIDE)              // 9216 per operand per stage
#define STGB ((OP_HALVES*2)*2)               // 36864 bytes
#define NSTG 3
#define GEMM_SMEM (NSTG*STGB)                // 110592
#define KITERS (HID/64)                      // 32
#define TSTR 136                             // epilogue tile stride (halves)

__global__ __launch_bounds__(256, 2) void hmma_gemm_kernel(
    const __half* __restrict__ A, const __half* __restrict__ B,
    const float* __restrict__ Dd, float* __restrict__ C, __half* __restrict__ Ch,
    int ldc, int mode)
{
    extern __shared__ char smraw[];
    uint32_t smb = smem_u32(smraw);
    int tid = threadIdx.x, wid = tid >> 5, lid = tid & 31;
    int mt = blockIdx.x, nt = blockIdx.y;

    int row_ = tid >> 3;          // base row (advances by 32 per i)
    int seg  = tid & 7;           // 8-half segment within 64-half row
    const __half* aptr = A + (size_t)(mt*128 + row_) * HID + seg*8;
    const __half* bptr = B + (size_t)(nt*128 + row_) * HID + seg*8;
    uint32_t aoff = (uint32_t)(row_*ASTRIDE + seg*8) * 2;
    uint32_t boff = (uint32_t)(OP_HALVES + row_*ASTRIDE + seg*8) * 2;

    #define LOADIT(it_, st_) do {                                        \
        uint32_t sb_ = smb + (uint32_t)(st_) * STGB;                     \
        int k0_ = (it_) * 64;                                            \
        _Pragma("unroll")                                                \
        for (int i_ = 0; i_ < 4; i_++) {                                 \
            cpasync16(sb_ + aoff + (uint32_t)(i_*32*ASTRIDE)*2,          \
                      aptr + (size_t)(i_*32)*HID + k0_);                 \
            cpasync16(sb_ + boff + (uint32_t)(i_*32*ASTRIDE)*2,          \
                      bptr + (size_t)(i_*32)*HID + k0_);                 \
        }                                                                \
    } while (0)

    int m0w = (wid & 1) * 64, n0w = (wid >> 1) * 32;
    int g = lid >> 3, r = lid & 7;
    uint32_t aBaseH = (uint32_t)((m0w + r + (g & 1)*8) * ASTRIDE + (g >> 1)*8);
    uint32_t bBaseH = (uint32_t)(OP_HALVES + (n0w + r + (g >> 1)*8) * ASTRIDE + (g & 1)*8);

    float acc[4][4][4];
    #pragma unroll
    for (int mi = 0; mi < 4; mi++)
        #pragma unroll
        for (int ni = 0; ni < 4; ni++)
            #pragma unroll
            for (int e = 0; e < 4; e++) acc[mi][ni][e] = 0.0f;

    LOADIT(0, 0);
    asm volatile("cp.async.commit_group;");
    LOADIT(1, 1);
    asm volatile("cp.async.commit_group;");

    int scur = 0, sld = 2;
    for (int it = 0; it < KITERS; it++) {
        asm volatile("cp.async.wait_group 1;");
        __syncthreads();
        uint32_t sb = smb + (uint32_t)scur * STGB;
        #pragma unroll
        for (int ks = 0; ks < 64; ks += 16) {
            uint32_t b[4][2];
            #pragma unroll
            for (int np = 0; np < 2; np++) {
                uint32_t r0, r1, r2, r3;
                ldm_x4(r0, r1, r2, r3, sb + 2*(bBaseH + (uint32_t)(np*16*ASTRIDE) + ks));
                b[np*2][0] = r0;   b[np*2][1] = r1;
                b[np*2+1][0] = r2; b[np*2+1][1] = r3;
            }
            #pragma unroll
            for (int mi = 0; mi < 4; mi++) {
                uint32_t a[4];
                ldm_x4(a[0], a[1], a[2], a[3], sb + 2*(aBaseH + (uint32_t)(mi*16*ASTRIDE) + ks));
                #pragma unroll
                for (int ni = 0; ni < 4; ni++) mma16816h(acc[mi][ni], a, b[ni]);
            }
        }
        int itn = it + 2;
        if (itn < KITERS) LOADIT(itn, sld);
        asm volatile("cp.async.commit_group;");
        scur = (scur == 2) ? 0 : scur + 1;
        sld  = (sld  == 2) ? 0 : sld  + 1;
    }

    int lr = lid >> 2, lc = (lid & 3) * 2;

    if (mode == 0) {
        #pragma unroll
        for (int mi = 0; mi < 4; mi++) {
            #pragma unroll
            for (int ni = 0; ni < 4; ni++) {
                int row0 = mt*128 + m0w + mi*16 + lr;
                int col  = nt*128 + n0w + ni*8 + lc;
                float2 v0 = make_float2(acc[mi][ni][0], acc[mi][ni][1]);
                float2 v1 = make_float2(acc[mi][ni][2], acc[mi][ni][3]);
                if (Dd) {
                    float2 d0 = *(const float2*)(Dd + (size_t)row0 * ldc + col);
                    float2 d1 = *(const float2*)(Dd + (size_t)(row0 + 8) * ldc + col);
                    v0.x += d0.x; v0.y += d0.y;
                    v1.x += d1.x; v1.y += d1.y;
                }
                *(float2*)(C + (size_t)row0 * ldc + col)       = v0;
                *(float2*)(C + (size_t)(row0 + 8) * ldc + col) = v1;
            }
        }
    } else if (mode == 3) {
        // interleaved (g1,g3) pairs: col even = g1, col+1 = g3 of unit col/2
        #pragma unroll
        for (int mi = 0; mi < 4; mi++) {
            #pragma unroll
            for (int ni = 0; ni < 4; ni++) {
                int row0 = mt*128 + m0w + mi*16 + lr;
                int unit = nt*64 + (n0w >> 1) + ni*4 + (lid & 3);
                float a0 = acc[mi][ni][0], b0 = acc[mi][ni][1];
                float a1 = acc[mi][ni][2], b1 = acc[mi][ni][3];
                float s0 = (a0 / (1.0f + expf(-a0))) * b0;
                float s1 = (a1 / (1.0f + expf(-a1))) * b1;
                Ch[(size_t)row0 * HID + unit]       = __float2half_rn(s0);
                Ch[(size_t)(row0 + 8) * HID + unit] = __float2half_rn(s1);
            }
        }
    } else {
        // mode 2: QKV epilogue. Stage tile through smem (reuse pipeline smem).
        __syncthreads();
        __half* stile = (__half*)smraw;
        #pragma unroll
        for (int mi = 0; mi < 4; mi++) {
            #pragma unroll
            for (int ni = 0; ni < 4; ni++) {
                int rl = m0w + mi*16 + lr;
                int cl = n0w + ni*8 + lc;
                *(__half2*)&stile[rl*TSTR + cl] =
                    __floats2half2_rn(acc[mi][ni][0], acc[mi][ni][1]);
                *(__half2*)&stile[(rl + 8)*TSTR + cl] =
                    __floats2half2_rn(acc[mi][ni][2], acc[mi][ni][3]);
            }
        }
        __syncthreads();
        int part = nt >> 4;          // 0=q, 1=k, 2=v
        int hh = nt & 15;
        int token0 = mt * 128;
        int b = token0 >> 11;
        int s0 = token0 & (SEQ - 1);
        if (part < 2) {
            float qs = (part == 0) ? 0.08838834764831845f : 1.0f;
            __half* dst = (part == 0 ? g_q2 : g_k2)
                        + (size_t)(b*NHEADS + hh) * SEQ * HDIM;
            #pragma unroll 4
            for (int j = 0; j < 32; j++) {
                int idx = tid + 256*j;
                int row = idx >> 6, i = idx & 63;
                int s = s0 + row;
                float c  = g_cos[s*64 + i];
                float sn = g_sin[s*64 + i];
                float x1 = __half2float(stile[row*TSTR + i]);
                float x2 = __half2float(stile[row*TSTR + i + 64]);
                dst[(size_t)s*HDIM + i]      = __float2half_rn((x1*c - x2*sn) * qs);
                dst[(size_t)s*HDIM + i + 64] = __float2half_rn((x2*c + x1*sn) * qs);
            }
        } else {
            __half* vb = g_vt + (size_t)(b*NHEADS + hh) * HDIM * SEQ;
            #pragma unroll 4
            for (int j = 0; j < 32; j++) {
                int idx = tid + 256*j;
                int d = idx >> 6, s2 = idx & 63;
                int srow = s2 * 2;
                __half2 v;
                v.x = stile[srow*TSTR + d];
                v.y = stile[(srow + 1)*TSTR + d];
                *(__half2*)&vb[(size_t)d*SEQ + s0 + srow] = v;
            }
        }
    }
    #undef LOADIT
}

// ---------------------------------------------------------------------------
// HMMA flash attention, single-pass fp16 (proven R7-R14); occ 2.
// ---------------------------------------------------------------------------
#define QS_STR 136
#define KS_STR 136
#define VS_STR 72
#define QS_OFF 0
#define KS_OFF (128*QS_STR)              // halves
#define KS_SZ  (64*KS_STR)
#define VS_OFF (KS_OFF + 2*KS_SZ)
#define VS_SZ  (128*VS_STR)
#define ATTN_SMEM ((VS_OFF + 2*VS_SZ)*2) // 106496 bytes

__global__ __launch_bounds__(256, 2) void attn_hmma_kernel(
    const __half* __restrict__ q2g, const __half* __restrict__ k2g,
    const __half* __restrict__ vtg, __half* __restrict__ ctxh)
{
    extern __shared__ char smraw[];
    uint32_t smb = smem_u32(smraw);
    int tid = threadIdx.x, wid = tid >> 5, lid = tid & 31;
    int qt = blockIdx.x, hh = blockIdx.y, b = blockIdx.z;
    int bh = b*NHEADS + hh;
    const __half* qbase = q2g + ((size_t)bh*SEQ + qt*128) * HDIM;
    const __half* kbase = k2g + (size_t)bh*SEQ * HDIM;
    const __half* vbase = vtg + (size_t)bh*HDIM*SEQ;

    #define LOAD_KT(st_, s0_) do {                                              \
        _Pragma("unroll")                                                       \
        for (int i_ = 0; i_ < 4; i_++) {                                        \
            int idx_ = tid + 256*i_; int row_ = idx_ >> 4, seg_ = idx_ & 15;    \
            cpasync16(smb + 2*(KS_OFF + (st_)*KS_SZ + row_*KS_STR + seg_*8),    \
                      kbase + ((size_t)((s0_) + row_))*HDIM + seg_*8);          \
        } } while (0)
    #define LOAD_VT(st_, s0_) do {                                              \
        _Pragma("unroll")                                                       \
        for (int i_ = 0; i_ < 4; i_++) {                                        \
            int idx_ = tid + 256*i_; int dr_ = idx_ >> 3, seg_ = idx_ & 7;      \
            cpasync16(smb + 2*(VS_OFF + (st_)*VS_SZ + dr_*VS_STR + seg_*8),     \
                      vbase + (size_t)dr_*SEQ + (s0_) + seg_*8);                \
        } } while (0)

    #pragma unroll
    for (int i = 0; i < 8; i++) {
        int idx = tid + 256*i; int row = idx >> 4, seg = idx & 15;
        cpasync16(smb + 2*(QS_OFF + row*QS_STR + seg*8),
                  qbase + (size_t)row*HDIM + seg*8);
    }
    LOAD_KT(0, 0); LOAD_VT(0, 0);
    asm volatile("cp.async.commit_group;");
    LOAD_KT(1, 64); LOAD_VT(1, 64);
    asm volatile("cp.async.commit_group;");

    int g = lid >> 3, r = lid & 7;
    uint32_t aQ = smb + 2*(QS_OFF + (uint32_t)((wid*16 + r + (g&1)*8)*QS_STR + (g>>1)*8));
    uint32_t bK = smb + 2*(KS_OFF + (uint32_t)((r + (g>>1)*8)*KS_STR + (g&1)*8));
    uint32_t bV = smb + 2*(VS_OFF + (uint32_t)((r + (g>>1)*8)*VS_STR + (g&1)*8));

    float oacc[16][4];
    #pragma unroll
    for (int n = 0; n < 16; n++)
        #pragma unroll
        for (int e = 0; e < 4; e++) oacc[n][e] = 0.0f;
    float m0 = -INFINITY, m1 = -INFINITY, l0 = 0.0f, l1 = 0.0f;

    for (int it = 0; it < SEQ/64; it++) {
        asm volatile("cp.async.wait_group 1;");
        __syncthreads();
        uint32_t kst = (uint32_t)((it & 1) * KS_SZ) * 2;
        uint32_t vst = (uint32_t)((it & 1) * VS_SZ) * 2;

        float sacc[8][4];
        #pragma unroll
        for (int n = 0; n < 8; n++)
            #pragma unroll
            for (int e = 0; e < 4; e++) sacc[n][e] = 0.0f;

        #pragma unroll
        for (int ks = 0; ks < 8; ks++) {
            uint32_t bfr[8][2];
            #pragma unroll
            for (int np = 0; np < 4; np++) {
                uint32_t r0,r1,r2,r3;
                ldm_x4(r0,r1,r2,r3, bK + kst + 2*(uint32_t)(np*16*KS_STR + ks*16));
                bfr[np*2][0]=r0; bfr[np*2][1]=r1; bfr[np*2+1][0]=r2; bfr[np*2+1][1]=r3;
            }
            uint32_t a[4];
            ldm_x4(a[0],a[1],a[2],a[3], aQ + 2*(uint32_t)(ks*16));
            #pragma unroll
            for (int n = 0; n < 8; n++) mma16816h(sacc[n], a, bfr[n]);
        }

        float mt0 = -INFINITY, mt1 = -INFINITY;
        #pragma unroll
        for (int n = 0; n < 8; n++) {
            mt0 = fmaxf(mt0, fmaxf(sacc[n][0], sacc[n][1]));
            mt1 = fmaxf(mt1, fmaxf(sacc[n][2], sacc[n][3]));
        }
        mt0 = fmaxf(mt0, __shfl_xor_sync(0xffffffffu, mt0, 1));
        mt0 = fmaxf(mt0, __shfl_xor_sync(0xffffffffu, mt0, 2));
        mt1 = fmaxf(mt1, __shfl_xor_sync(0xffffffffu, mt1, 1));
        mt1 = fmaxf(mt1, __shfl_xor_sync(0xffffffffu, mt1, 2));
        float mn0 = fmaxf(m0, mt0), mn1 = fmaxf(m1, mt1);
        float al0 = __expf(m0 - mn0), al1 = __expf(m1 - mn1);
        m0 = mn0; m1 = mn1;

        uint32_t ph0[8], ph1[8];
        float rs0 = 0.0f, rs1 = 0.0f;
        #pragma unroll
        for (int n = 0; n < 8; n++) {
            float p0 = __expf(sacc[n][0] - mn0);
            float p1 = __expf(sacc[n][1] - mn0);
            float p2 = __expf(sacc[n][2] - mn1);
            float p3 = __expf(sacc[n][3] - mn1);
            rs0 += p0 + p1; rs1 += p2 + p3;
            ph0[n] = packh(p0, p1);
            ph1[n] = packh(p2, p3);
        }
        rs0 += __shfl_xor_sync(0xffffffffu, rs0, 1);
        rs0 += __shfl_xor_sync(0xffffffffu, rs0, 2);
        rs1 += __shfl_xor_sync(0xffffffffu, rs1, 1);
        rs1 += __shfl_xor_sync(0xffffffffu, rs1, 2);
        l0 = l0*al0 + rs0; l1 = l1*al1 + rs1;
        #pragma unroll
        for (int n = 0; n < 16; n++) {
            oacc[n][0] *= al0; oacc[n][1] *= al0;
            oacc[n][2] *= al1; oacc[n][3] *= al1;
        }

        #pragma unroll
        for (int ks = 0; ks < 4; ks++) {
            uint32_t a[4] = { ph0[2*ks], ph1[2*ks], ph0[2*ks+1], ph1[2*ks+1] };
            #pragma unroll
            for (int np = 0; np < 8; np++) {
                uint32_t r0,r1,r2,r3;
                ldm_x4(r0,r1,r2,r3, bV + vst + 2*(uint32_t)(np*16*VS_STR + ks*16));
                uint32_t b0[2] = {r0, r1}, b1[2] = {r2, r3};
                mma16816h(oacc[np*2], a, b0); mma16816h(oacc[np*2+1], a, b1);
            }
        }

        __syncthreads();
        int itn = it + 2;
        if (itn < SEQ/64) {
            LOAD_KT(itn & 1, itn*64); LOAD_VT(itn & 1, itn*64);
        }
        asm volatile("cp.async.commit_group;");
    }

    float inv0 = 1.0f / l0, inv1 = 1.0f / l1;
    int row0 = qt*128 + wid*16 + (lid >> 2);
    int colb = 2*(lid & 3);
    __half* cb = ctxh + ((size_t)(b*SEQ) + row0) * HID + hh*HDIM;
    #pragma unroll
    for (int n = 0; n < 16; n++) {
        *(__half2*)(cb + n*8 + colb) =
            __floats2half2_rn(oacc[n][0]*inv0, oacc[n][1]*inv0);
        *(__half2*)(cb + (size_t)8*HID + n*8 + colb) =
            __floats2half2_rn(oacc[n][2]*inv1, oacc[n][3]*inv1);
    }
    #undef LOAD_KT
    #undef LOAD_VT
}

// ---------------------------------------------------------------------------
// Launch
// ---------------------------------------------------------------------------
extern "C" void kernel_launch(void* const* d_in, const int* in_sizes, int n_in,
                              void* d_out, int out_size)
{
    (void)in_sizes; (void)n_in; (void)out_size;
    const float* hs  = (const float*)d_in[0];
    const float* Wq  = (const float*)d_in[1];
    const float* Wk  = (const float*)d_in[2];
    const float* Wv  = (const float*)d_in[3];
    const float* Wo  = (const float*)d_in[4];
    const float* w1  = (const float*)d_in[5];
    const float* w2  = (const float*)d_in[6];
    const float* w3  = (const float*)d_in[7];
    const float* ln1 = (const float*)d_in[8];
    const float* ln2 = (const float*)d_in[9];
    float* out = (float*)d_out;

    __half *xh, *ctxh, *sx;
    __half *Wqkv, *Wo2, *w13, *w22;
    __half *q2, *k2, *vt;
    float *h;
    cudaGetSymbolAddress((void**)&xh,   g_xh);
    cudaGetSymbolAddress((void**)&ctxh, g_ctxh);
    cudaGetSymbolAddress((void**)&sx,   g_sx);
    cudaGetSymbolAddress((void**)&Wqkv, g_Wqkv);
    cudaGetSymbolAddress((void**)&Wo2,  g_Wo2);
    cudaGetSymbolAddress((void**)&w13,  g_w13);
    cudaGetSymbolAddress((void**)&w22,  g_w22);
    cudaGetSymbolAddress((void**)&q2,   g_q2);
    cudaGetSymbolAddress((void**)&k2,   g_k2);
    cudaGetSymbolAddress((void**)&vt,   g_vt);
    cudaGetSymbolAddress((void**)&h,    g_h);

    cudaFuncSetAttribute(attn_hmma_kernel, cudaFuncAttributeMaxDynamicSharedMemorySize, ATTN_SMEM);
    cudaFuncSetAttribute(hmma_gemm_kernel, cudaFuncAttributeMaxDynamicSharedMemorySize, GEMM_SMEM);

    WArgs wa;
    wa.src[0] = Wq; wa.dst[0] = Wqkv;                        wa.rs[0] = 1; wa.ro[0] = 0;
    wa.src[1] = Wk; wa.dst[1] = Wqkv + (size_t)HID*HID;      wa.rs[1] = 1; wa.ro[1] = 0;
    wa.src[2] = Wv; wa.dst[2] = Wqkv + (size_t)2*HID*HID;    wa.rs[2] = 1; wa.ro[2] = 0;
    wa.src[3] = Wo; wa.dst[3] = Wo2;                         wa.rs[3] = 1; wa.ro[3] = 0;
    wa.src[4] = w1; wa.dst[4] = w13;                         wa.rs[4] = 2; wa.ro[4] = 0;
    wa.src[5] = w3; wa.dst[5] = w13;                         wa.rs[5] = 2; wa.ro[5] = 1;
    wa.src[6] = w2; wa.dst[6] = w22;                         wa.rs[6] = 1; wa.ro[6] = 0;

    rope_table_kernel<<<(SEQ * 64 + 255) / 256, 256>>>();
    wtrans_all_kernel<<<dim3(HID/64, HID/64, 7), 256>>>(wa);

    rmsnorm_h_kernel<<<MROWS, 256>>>(hs, ln1, xh);

    // QKV fused GEMM + rope/transpose epilogue: writes g_q2, g_k2, g_vt
    hmma_gemm_kernel<<<dim3(MROWS/128, 3*HID/128), 256, GEMM_SMEM>>>(
        xh, Wqkv, nullptr, nullptr, nullptr, 0, 2);

    attn_hmma_kernel<<<dim3(SEQ/128, NHEADS, BATCH), 256, ATTN_SMEM>>>(q2, k2, vt, ctxh);

    hmma_gemm_kernel<<<dim3(MROWS/128, HID/128), 256, GEMM_SMEM>>>(
        ctxh, Wo2, hs, h, nullptr, HID, 0);              // h = hs + ctx@Wo

    rmsnorm_h_kernel<<<MROWS, 256>>>(h, ln2, xh);        // y

    // w1/w3 interleaved GEMM + fused silu epilogue: writes sx directly
    hmma_gemm_kernel<<<dim3(MROWS/128, 2*HID/128), 256, GEMM_SMEM>>>(
        xh, w13, nullptr, nullptr, sx, 0, 3);

    hmma_gemm_kernel<<<dim3(MROWS/128, HID/128), 256, GEMM_SMEM>>>(
        sx, w22, h, out, nullptr, HID, 0);               // out = h + mlp
}